// round 4
// baseline (speedup 1.0000x reference)
#include <cuda_runtime.h>
#include <math.h>
#include <stdint.h>

// Problem constants
#define Bn 4
#define Sn 1024
#define Tn 4096          // Bn*Sn tokens
#define Hn 512
#define En 8
#define Fn 2048
#define NBUCK 32         // En*Bn  (expert, batch) buckets
#define CAPn 1024        // max tokens per bucket = Sn

// ---------------- scratch (__device__ globals; no allocation) ----------------
__device__ float g_K [(size_t)En*Tn*Hn];        // 64 MB
__device__ float g_V [(size_t)En*Tn*Hn];        // 64 MB
__device__ float g_q [(size_t)NBUCK*CAPn*Hn];   // 64 MB
__device__ float g_sc[(size_t)NBUCK*CAPn*Sn];   // 128 MB
__device__ float g_h1[(size_t)NBUCK*CAPn*Fn];   // 256 MB
__device__ float g_h2[(size_t)NBUCK*CAPn*Hn];   // 64 MB
__device__ float g_a [(size_t)NBUCK*CAPn*Hn];   // 64 MB
__device__ int   g_cnt[NBUCK];
__device__ int   g_tok[NBUCK*CAPn];
__device__ float g_wt [NBUCK*CAPn];
__device__ float g_imp[En];

// ---------------- small kernels ----------------
__global__ void reset_kernel() {
    int i = threadIdx.x;
    if (i < NBUCK) g_cnt[i] = 0;
    if (i < En)    g_imp[i] = 0.f;
}

__global__ void zero_kernel(float* __restrict__ out, int n) {
    int i = blockIdx.x * blockDim.x + threadIdx.x;
    if (i < n) out[i] = 0.f;
}

// Router: one warp per token. Exact fp32.
__global__ void router_kernel(const float* __restrict__ x,
                              const float* __restrict__ Wg,
                              const float* __restrict__ bg)
{
    int warp = (blockIdx.x * blockDim.x + threadIdx.x) >> 5;
    int lane = threadIdx.x & 31;
    if (warp >= Tn) return;
    const int t = warp;

    float acc[En];
#pragma unroll
    for (int e = 0; e < En; e++) acc[e] = 0.f;

    for (int h = lane; h < Hn; h += 32) {
        float xv = x[(size_t)t * Hn + h];
        float4 w0 = *(const float4*)(Wg + (size_t)h * En);
        float4 w1 = *(const float4*)(Wg + (size_t)h * En + 4);
        acc[0] += xv * w0.x; acc[1] += xv * w0.y; acc[2] += xv * w0.z; acc[3] += xv * w0.w;
        acc[4] += xv * w1.x; acc[5] += xv * w1.y; acc[6] += xv * w1.z; acc[7] += xv * w1.w;
    }
#pragma unroll
    for (int off = 16; off > 0; off >>= 1) {
#pragma unroll
        for (int e = 0; e < En; e++)
            acc[e] += __shfl_xor_sync(0xffffffffu, acc[e], off);
    }
    if (lane != 0) return;

    float p[En];
    float m = -1e30f;
#pragma unroll
    for (int e = 0; e < En; e++) { p[e] = acc[e] + bg[e]; m = fmaxf(m, p[e]); }
    float s = 0.f;
#pragma unroll
    for (int e = 0; e < En; e++) { p[e] = expf(p[e] - m); s += p[e]; }
    float inv = 1.0f / s;
#pragma unroll
    for (int e = 0; e < En; e++) { p[e] *= inv; atomicAdd(&g_imp[e], p[e]); }

    int i1 = 0;
#pragma unroll
    for (int e = 1; e < En; e++) if (p[e] > p[i1]) i1 = e;
    int i2 = (i1 == 0) ? 1 : 0;
#pragma unroll
    for (int e = 0; e < En; e++) if (e != i1 && p[e] > p[i2]) i2 = e;

    float denom = p[i1] + p[i2];
    int b = t >> 10;
    int bk1 = i1 * Bn + b;
    int pos1 = atomicAdd(&g_cnt[bk1], 1);
    g_tok[bk1 * CAPn + pos1] = t;
    g_wt [bk1 * CAPn + pos1] = p[i1] / denom;
    int bk2 = i2 * Bn + b;
    int pos2 = atomicAdd(&g_cnt[bk2], 1);
    g_tok[bk2 * CAPn + pos2] = t;
    g_wt [bk2 * CAPn + pos2] = p[i2] / denom;
}

// Row softmax over scores (length Sn = 1024), 256 threads, 4 elems/thread.
__global__ void softmax_kernel()
{
    int bkt = blockIdx.x >> 10;
    int r   = blockIdx.x & (CAPn - 1);
    if (r >= g_cnt[bkt]) return;
    float* row = g_sc + ((size_t)bkt * CAPn + r) * Sn;
    int tid = threadIdx.x;

    float4 v = *(float4*)(row + tid * 4);
    float m = fmaxf(fmaxf(v.x, v.y), fmaxf(v.z, v.w));

    __shared__ float sm[8];
    __shared__ float bcast;
#pragma unroll
    for (int off = 16; off > 0; off >>= 1)
        m = fmaxf(m, __shfl_xor_sync(0xffffffffu, m, off));
    if ((tid & 31) == 0) sm[tid >> 5] = m;
    __syncthreads();
    if (tid == 0) {
        float mm = sm[0];
#pragma unroll
        for (int k = 1; k < 8; k++) mm = fmaxf(mm, sm[k]);
        bcast = mm;
    }
    __syncthreads();
    float bm = bcast;

    v.x = expf(v.x - bm); v.y = expf(v.y - bm);
    v.z = expf(v.z - bm); v.w = expf(v.w - bm);
    float ssum = v.x + v.y + v.z + v.w;
#pragma unroll
    for (int off = 16; off > 0; off >>= 1)
        ssum += __shfl_xor_sync(0xffffffffu, ssum, off);
    if ((tid & 31) == 0) sm[tid >> 5] = ssum;
    __syncthreads();
    if (tid == 0) {
        float tt = 0.f;
#pragma unroll
        for (int k = 0; k < 8; k++) tt += sm[k];
        bcast = 1.0f / tt;
    }
    __syncthreads();
    float invs = bcast;
    v.x *= invs; v.y *= invs; v.z *= invs; v.w *= invs;
    *(float4*)(row + tid * 4) = v;
}

__global__ void finalize_kernel(float* __restrict__ out, int out_size)
{
    if (threadIdx.x == 0 && out_size > Tn * Hn) {
        float loss = 0.f;
        for (int e = 0; e < En; e++) {
            int a = 0;
            for (int b = 0; b < Bn; b++) a += g_cnt[e * Bn + b];
            loss += ((float)a / (float)Tn) * (g_imp[e] / (float)Tn);
        }
        out[Tn * Hn] = (float)En * loss;
    }
}

// ---------------- tf32 mma.sync GEMM: 128x128 tile, 4 warps, warp 64x64 ----------------
enum { KK = 0, KV = 1, KQ = 2, KF1 = 3, KF2 = 4, KSC = 5, KPV = 6, KO = 7 };

__device__ __forceinline__ float tf32f(float x) {
    uint32_t u;
    asm("cvt.rna.tf32.f32 %0, %1;" : "=r"(u) : "f"(x));
    return __uint_as_float(u);
}

__device__ __forceinline__ void mma_tf32_16x8x8(float* c, const uint32_t* a, const uint32_t* b) {
    asm volatile(
        "mma.sync.aligned.m16n8k8.row.col.f32.tf32.tf32.f32 "
        "{%0,%1,%2,%3}, {%4,%5,%6,%7}, {%8,%9}, {%0,%1,%2,%3};"
        : "+f"(c[0]), "+f"(c[1]), "+f"(c[2]), "+f"(c[3])
        : "r"(a[0]), "r"(a[1]), "r"(a[2]), "r"(a[3]), "r"(b[0]), "r"(b[1]));
}

#define APAD 136   // A row stride (136 mod 32 == 8 -> reads conflict-free)

template <int KIND>
__global__ __launch_bounds__(128, 2)
void gemm_kernel(const float* __restrict__ Xin, const float* __restrict__ W,
                 const float* __restrict__ bias, float* __restrict__ outp)
{
    constexpr bool BUCKET = (KIND != KK && KIND != KV);
    constexpr bool TRANSB = (KIND == KSC);
    constexpr int  KDIM = (KIND == KF2) ? Fn : (KIND == KPV ? Sn : Hn);
    constexpr int  LDB  = (KIND == KF1) ? Fn : Hn;

    const int tid  = threadIdx.x;
    const int wid  = tid >> 5;
    const int lane = tid & 31;
    const int z = blockIdx.z;
    int e, bb = 0, M;
    if (BUCKET) {
        e = z >> 2; bb = z & 3;
        M = g_cnt[z];
        if ((int)(blockIdx.x * 128) >= M) return;
    } else {
        e = z; M = Tn;
    }

    const float* Bptr;
    if      (KIND == KK || KIND == KV || KIND == KQ || KIND == KO) Bptr = W + (size_t)e * Hn * Hn;
    else if (KIND == KF1) Bptr = W + (size_t)e * Hn * Fn;
    else if (KIND == KF2) Bptr = W + (size_t)e * Fn * Hn;
    else if (KIND == KSC) Bptr = g_K + ((size_t)e * Tn + (size_t)bb * Sn) * Hn;
    else                  Bptr = g_V + ((size_t)e * Tn + (size_t)bb * Sn) * Hn;  // KPV

    const int row0 = blockIdx.x * 128;
    const int col0 = blockIdx.y * 128;

    // ---- A loader: one row per thread ----
    const int grow = row0 + tid;
    const bool aval = grow < M;
    const float* aRow = nullptr;
    if (aval) {
        if      (KIND == KQ || KIND == KF1)  aRow = Xin + (size_t)g_tok[z * CAPn + grow] * Hn;
        else if (KIND == KK || KIND == KV)   aRow = Xin + (size_t)grow * Hn;
        else if (KIND == KF2)                aRow = g_h1 + ((size_t)z * CAPn + grow) * Fn;
        else if (KIND == KSC)                aRow = g_q  + ((size_t)z * CAPn + grow) * Hn;
        else if (KIND == KPV)                aRow = g_sc + ((size_t)z * CAPn + grow) * Sn;
        else                                 aRow = g_a  + ((size_t)z * CAPn + grow) * Hn;  // KO
    }
    // ---- B loader indices ----
    const int bk = tid >> 3;           // normal: B k row 0..15
    const int g0 = tid & 7;            // normal: granule base; granules g0, g0+8, g0+16, g0+24
    const int bswz = 2 * (bk & 3);     // normal store swizzle
    // TRANSB: one n-row per thread: n_local = tid

    __shared__ __align__(16) float As[16 * APAD];
    __shared__ __align__(16) float Bs[16 * 128];

    float acc[4][8][4];
#pragma unroll
    for (int i = 0; i < 4; i++)
#pragma unroll
        for (int j = 0; j < 8; j++)
#pragma unroll
            for (int k = 0; k < 4; k++) acc[i][j][k] = 0.f;

    const int wm  = (wid >> 1) * 64;   // warp m offset
    const int wn  = (wid & 1) * 64;    // warp n offset
    const int grp = lane >> 2;
    const int tg  = lane & 3;

    // fragment read bases
    const int abase = tg * APAD + wm + grp;                       // + ks*APAD + mt*16 (+8 / +4*APAD)
    int bbase[8];
#pragma unroll
    for (int nt = 0; nt < 8; nt++) {
        int gran = (((wn >> 2) + nt * 2 + (grp >> 2)) ^ (2 * tg));
        bbase[nt] = tg * 128 + gran * 4 + (grp & 3);              // + ks*128 (+4*128)
    }

    // ---- prefetch chunk 0 ----
    float4 pa[4], pb[4];
#pragma unroll
    for (int j = 0; j < 4; j++) pa[j] = make_float4(0.f, 0.f, 0.f, 0.f);
    if (aval) {
#pragma unroll
        for (int j = 0; j < 4; j++) pa[j] = *(const float4*)(aRow + j * 4);
    }
    if (!TRANSB) {
        const float* bs = Bptr + (size_t)bk * LDB + col0;
#pragma unroll
        for (int j = 0; j < 4; j++) pb[j] = *(const float4*)(bs + (g0 + 8 * j) * 4);
    } else {
        const float* bs = Bptr + (size_t)(col0 + tid) * LDB;
#pragma unroll
        for (int j = 0; j < 4; j++) pb[j] = *(const float4*)(bs + j * 4);
    }

    for (int kt = 0; kt < KDIM; kt += 16) {
        // ---- store prefetched tile (tf32-rounded) ----
#pragma unroll
        for (int j = 0; j < 4; j++) {
            As[(j * 4 + 0) * APAD + tid] = tf32f(pa[j].x);
            As[(j * 4 + 1) * APAD + tid] = tf32f(pa[j].y);
            As[(j * 4 + 2) * APAD + tid] = tf32f(pa[j].z);
            As[(j * 4 + 3) * APAD + tid] = tf32f(pa[j].w);
        }
        if (!TRANSB) {
#pragma unroll
            for (int j = 0; j < 4; j++) {
                int gw = ((g0 + 8 * j) ^ bswz) * 4;
                float4 v = make_float4(tf32f(pb[j].x), tf32f(pb[j].y),
                                       tf32f(pb[j].z), tf32f(pb[j].w));
                *(float4*)&Bs[bk * 128 + gw] = v;
            }
        } else {
#pragma unroll
            for (int j = 0; j < 4; j++) {
                float bv[4] = {pb[j].x, pb[j].y, pb[j].z, pb[j].w};
#pragma unroll
                for (int c = 0; c < 4; c++) {
                    int k = j * 4 + c;
                    Bs[k * 128 + (((tid >> 2) ^ (2 * c)) * 4) + (tid & 3)] = tf32f(bv[c]);
                }
            }
        }
        __syncthreads();

        // ---- prefetch next chunk ----
        if (kt + 16 < KDIM) {
            if (aval) {
#pragma unroll
                for (int j = 0; j < 4; j++) pa[j] = *(const float4*)(aRow + kt + 16 + j * 4);
            }
            if (!TRANSB) {
                const float* bs = Bptr + (size_t)(kt + 16 + bk) * LDB + col0;
#pragma unroll
                for (int j = 0; j < 4; j++) pb[j] = *(const float4*)(bs + (g0 + 8 * j) * 4);
            } else {
                const float* bs = Bptr + (size_t)(col0 + tid) * LDB + kt + 16;
#pragma unroll
                for (int j = 0; j < 4; j++) pb[j] = *(const float4*)(bs + j * 4);
            }
        }

        // ---- compute 2 k8-steps ----
#pragma unroll
        for (int ks = 0; ks < 16; ks += 8) {
            uint32_t af[4][4], bf[8][2];
#pragma unroll
            for (int mt = 0; mt < 4; mt++) {
                const int ai = abase + ks * APAD + mt * 16;
                af[mt][0] = __float_as_uint(As[ai]);
                af[mt][1] = __float_as_uint(As[ai + 8]);
                af[mt][2] = __float_as_uint(As[ai + 4 * APAD]);
                af[mt][3] = __float_as_uint(As[ai + 4 * APAD + 8]);
            }
#pragma unroll
            for (int nt = 0; nt < 8; nt++) {
                const int bi = bbase[nt] + ks * 128;
                bf[nt][0] = __float_as_uint(Bs[bi]);
                bf[nt][1] = __float_as_uint(Bs[bi + 4 * 128]);
            }
#pragma unroll
            for (int mt = 0; mt < 4; mt++)
#pragma unroll
                for (int nt = 0; nt < 8; nt++)
                    mma_tf32_16x8x8(acc[mt][nt], af[mt], bf[nt]);
        }
        __syncthreads();
    }

    // ---------------- epilogue ----------------
    // lane owns rows: row0+wm+mt*16+grp (+8), cols: col0+wn+nt*8+tg*2 (+1)
#pragma unroll
    for (int mt = 0; mt < 4; mt++) {
#pragma unroll
        for (int half = 0; half < 2; half++) {
            const int r = row0 + wm + mt * 16 + grp + half * 8;
            if (BUCKET && r >= M) continue;

            if (KIND == KK || KIND == KV) {
                float* C = (KIND == KK ? g_K : g_V) + (size_t)e * Tn * Hn + (size_t)r * Hn;
                const float* bp = bias + (size_t)e * Hn;
#pragma unroll
                for (int nt = 0; nt < 8; nt++) {
                    const int c = col0 + wn + nt * 8 + tg * 2;
                    float2 bv = *(const float2*)(bp + c);
                    float2 v = make_float2(acc[mt][nt][half*2]   + bv.x,
                                           acc[mt][nt][half*2+1] + bv.y);
                    *(float2*)(C + c) = v;
                }
            } else if (KIND == KQ) {
                float* C = g_q + ((size_t)z * CAPn + r) * Hn;
                const float* bp = bias + (size_t)e * Hn;
#pragma unroll
                for (int nt = 0; nt < 8; nt++) {
                    const int c = col0 + wn + nt * 8 + tg * 2;
                    float2 bv = *(const float2*)(bp + c);
                    float2 v = make_float2(acc[mt][nt][half*2]   + bv.x,
                                           acc[mt][nt][half*2+1] + bv.y);
                    *(float2*)(C + c) = v;
                }
            } else if (KIND == KF1) {
                float* C = g_h1 + ((size_t)z * CAPn + r) * Fn;
                const float* bp = bias + (size_t)e * Fn;
#pragma unroll
                for (int nt = 0; nt < 8; nt++) {
                    const int c = col0 + wn + nt * 8 + tg * 2;
                    float2 bv = *(const float2*)(bp + c);
                    float t0 = acc[mt][nt][half*2]   + bv.x;
                    float t1 = acc[mt][nt][half*2+1] + bv.y;
                    float2 v;
                    v.x = 0.5f * t0 * (1.0f + erff(t0 * 0.70710678118654752f));
                    v.y = 0.5f * t1 * (1.0f + erff(t1 * 0.70710678118654752f));
                    *(float2*)(C + c) = v;
                }
            } else if (KIND == KF2) {
                float* C = g_h2 + ((size_t)z * CAPn + r) * Hn;
                const float* bp = bias + (size_t)e * Hn;
#pragma unroll
                for (int nt = 0; nt < 8; nt++) {
                    const int c = col0 + wn + nt * 8 + tg * 2;
                    float2 bv = *(const float2*)(bp + c);
                    float2 v = make_float2(acc[mt][nt][half*2]   + bv.x,
                                           acc[mt][nt][half*2+1] + bv.y);
                    *(float2*)(C + c) = v;
                }
            } else if (KIND == KSC) {
                const float scl = 0.044194173824159216f;  // 1/sqrt(512)
                float* C = g_sc + ((size_t)z * CAPn + r) * Sn;
#pragma unroll
                for (int nt = 0; nt < 8; nt++) {
                    const int c = col0 + wn + nt * 8 + tg * 2;
                    float2 v = make_float2(acc[mt][nt][half*2]   * scl,
                                           acc[mt][nt][half*2+1] * scl);
                    *(float2*)(C + c) = v;
                }
            } else if (KIND == KPV) {
                float* C = g_a + ((size_t)z * CAPn + r) * Hn;
#pragma unroll
                for (int nt = 0; nt < 8; nt++) {
                    const int c = col0 + wn + nt * 8 + tg * 2;
                    float2 v = make_float2(acc[mt][nt][half*2],
                                           acc[mt][nt][half*2+1]);
                    *(float2*)(C + c) = v;
                }
            } else {  // KO
                const int tok = g_tok[z * CAPn + r];
                const float wt = g_wt[z * CAPn + r];
                const float* bp = bias + (size_t)e * Hn;
                const float* h2 = g_h2 + ((size_t)z * CAPn + r) * Hn;
                float* od = outp + (size_t)tok * Hn;
#pragma unroll
                for (int nt = 0; nt < 8; nt++) {
                    const int c = col0 + wn + nt * 8 + tg * 2;
                    float v0 = acc[mt][nt][half*2]   + bp[c]   + h2[c];
                    float v1 = acc[mt][nt][half*2+1] + bp[c+1] + h2[c+1];
                    atomicAdd(od + c,     wt * v0);
                    atomicAdd(od + c + 1, wt * v1);
                }
            }
        }
    }
}

// ---------------- launch ----------------
extern "C" void kernel_launch(void* const* d_in, const int* in_sizes, int n_in,
                              void* d_out, int out_size)
{
    const float* x    = (const float*)d_in[0];
    const float* Wg   = (const float*)d_in[1];
    const float* bg   = (const float*)d_in[2];
    const float* fc1w = (const float*)d_in[3];
    const float* fc1b = (const float*)d_in[4];
    const float* fc2w = (const float*)d_in[5];
    const float* fc2b = (const float*)d_in[6];
    const float* qw   = (const float*)d_in[7];
    const float* qb   = (const float*)d_in[8];
    const float* kw   = (const float*)d_in[9];
    const float* kb   = (const float*)d_in[10];
    const float* vw   = (const float*)d_in[11];
    const float* vb   = (const float*)d_in[12];
    const float* ow   = (const float*)d_in[13];
    const float* ob   = (const float*)d_in[14];
    float* out = (float*)d_out;

    reset_kernel<<<1, 64>>>();
    zero_kernel<<<(out_size + 255) / 256, 256>>>(out, out_size);
    router_kernel<<<Tn / 8, 256>>>(x, Wg, bg);

    dim3 gkv(Tn / 128, Hn / 128, En);
    gemm_kernel<KK><<<gkv, 128>>>(x, kw, kb, nullptr);
    gemm_kernel<KV><<<gkv, 128>>>(x, vw, vb, nullptr);

    dim3 gq(CAPn / 128, Hn / 128, NBUCK);
    gemm_kernel<KQ><<<gq, 128>>>(x, qw, qb, nullptr);

    dim3 gf1(CAPn / 128, Fn / 128, NBUCK);
    gemm_kernel<KF1><<<gf1, 128>>>(x, fc1w, fc1b, nullptr);

    dim3 gf2(CAPn / 128, Hn / 128, NBUCK);
    gemm_kernel<KF2><<<gf2, 128>>>(nullptr, fc2w, fc2b, nullptr);

    dim3 gsc(CAPn / 128, Sn / 128, NBUCK);
    gemm_kernel<KSC><<<gsc, 128>>>(nullptr, nullptr, nullptr, nullptr);

    softmax_kernel<<<NBUCK * CAPn, 256>>>();

    dim3 gpv(CAPn / 128, Hn / 128, NBUCK);
    gemm_kernel<KPV><<<gpv, 128>>>(nullptr, nullptr, nullptr, nullptr);

    dim3 go(CAPn / 128, Hn / 128, NBUCK);
    gemm_kernel<KO><<<go, 128>>>(nullptr, ow, ob, out);

    finalize_kernel<<<1, 32>>>(out, out_size);
}

// round 5
// speedup vs baseline: 1.2245x; 1.2245x over previous
#include <cuda_runtime.h>
#include <cuda_fp16.h>
#include <math.h>
#include <stdint.h>

// Problem constants
#define Bn 4
#define Sn 1024
#define Tn 4096          // Bn*Sn tokens
#define Hn 512
#define En 8
#define Fn 2048
#define NBUCK 32         // En*Bn  (expert, batch) buckets
#define CAPn 1024        // max tokens per bucket = Sn

// ---------------- scratch (__device__ globals; no allocation) ----------------
__device__ float g_K [(size_t)En*Tn*Hn];        // 64 MB
__device__ float g_V [(size_t)En*Tn*Hn];        // 64 MB
__device__ float g_q [(size_t)NBUCK*CAPn*Hn];   // 64 MB
__device__ float g_sc[(size_t)NBUCK*CAPn*Sn];   // 128 MB
__device__ float g_h1[(size_t)NBUCK*CAPn*Fn];   // 256 MB
__device__ float g_h2[(size_t)NBUCK*CAPn*Hn];   // 64 MB
__device__ float g_a [(size_t)NBUCK*CAPn*Hn];   // 64 MB
__device__ int   g_cnt[NBUCK];
__device__ int   g_tok[NBUCK*CAPn];
__device__ float g_wt [NBUCK*CAPn];
__device__ float g_imp[En];

// ---------------- small kernels ----------------
__global__ void reset_kernel() {
    int i = threadIdx.x;
    if (i < NBUCK) g_cnt[i] = 0;
    if (i < En)    g_imp[i] = 0.f;
}

__global__ void zero_kernel(float* __restrict__ out, int n) {
    int i = blockIdx.x * blockDim.x + threadIdx.x;
    if (i < n) out[i] = 0.f;
}

// Router: one warp per token. Exact fp32.
__global__ void router_kernel(const float* __restrict__ x,
                              const float* __restrict__ Wg,
                              const float* __restrict__ bg)
{
    int warp = (blockIdx.x * blockDim.x + threadIdx.x) >> 5;
    int lane = threadIdx.x & 31;
    if (warp >= Tn) return;
    const int t = warp;

    float acc[En];
#pragma unroll
    for (int e = 0; e < En; e++) acc[e] = 0.f;

    for (int h = lane; h < Hn; h += 32) {
        float xv = x[(size_t)t * Hn + h];
        float4 w0 = *(const float4*)(Wg + (size_t)h * En);
        float4 w1 = *(const float4*)(Wg + (size_t)h * En + 4);
        acc[0] += xv * w0.x; acc[1] += xv * w0.y; acc[2] += xv * w0.z; acc[3] += xv * w0.w;
        acc[4] += xv * w1.x; acc[5] += xv * w1.y; acc[6] += xv * w1.z; acc[7] += xv * w1.w;
    }
#pragma unroll
    for (int off = 16; off > 0; off >>= 1) {
#pragma unroll
        for (int e = 0; e < En; e++)
            acc[e] += __shfl_xor_sync(0xffffffffu, acc[e], off);
    }
    if (lane != 0) return;

    float p[En];
    float m = -1e30f;
#pragma unroll
    for (int e = 0; e < En; e++) { p[e] = acc[e] + bg[e]; m = fmaxf(m, p[e]); }
    float s = 0.f;
#pragma unroll
    for (int e = 0; e < En; e++) { p[e] = expf(p[e] - m); s += p[e]; }
    float inv = 1.0f / s;
#pragma unroll
    for (int e = 0; e < En; e++) { p[e] *= inv; atomicAdd(&g_imp[e], p[e]); }

    int i1 = 0;
#pragma unroll
    for (int e = 1; e < En; e++) if (p[e] > p[i1]) i1 = e;
    int i2 = (i1 == 0) ? 1 : 0;
#pragma unroll
    for (int e = 0; e < En; e++) if (e != i1 && p[e] > p[i2]) i2 = e;

    float denom = p[i1] + p[i2];
    int b = t >> 10;
    int bk1 = i1 * Bn + b;
    int pos1 = atomicAdd(&g_cnt[bk1], 1);
    g_tok[bk1 * CAPn + pos1] = t;
    g_wt [bk1 * CAPn + pos1] = p[i1] / denom;
    int bk2 = i2 * Bn + b;
    int pos2 = atomicAdd(&g_cnt[bk2], 1);
    g_tok[bk2 * CAPn + pos2] = t;
    g_wt [bk2 * CAPn + pos2] = p[i2] / denom;
}

// Row softmax over scores (length Sn = 1024), 256 threads, 4 elems/thread.
__global__ void softmax_kernel()
{
    int bkt = blockIdx.x >> 10;
    int r   = blockIdx.x & (CAPn - 1);
    if (r >= g_cnt[bkt]) return;
    float* row = g_sc + ((size_t)bkt * CAPn + r) * Sn;
    int tid = threadIdx.x;

    float4 v = *(float4*)(row + tid * 4);
    float m = fmaxf(fmaxf(v.x, v.y), fmaxf(v.z, v.w));

    __shared__ float sm[8];
    __shared__ float bcast;
#pragma unroll
    for (int off = 16; off > 0; off >>= 1)
        m = fmaxf(m, __shfl_xor_sync(0xffffffffu, m, off));
    if ((tid & 31) == 0) sm[tid >> 5] = m;
    __syncthreads();
    if (tid == 0) {
        float mm = sm[0];
#pragma unroll
        for (int k = 1; k < 8; k++) mm = fmaxf(mm, sm[k]);
        bcast = mm;
    }
    __syncthreads();
    float bm = bcast;

    v.x = expf(v.x - bm); v.y = expf(v.y - bm);
    v.z = expf(v.z - bm); v.w = expf(v.w - bm);
    float ssum = v.x + v.y + v.z + v.w;
#pragma unroll
    for (int off = 16; off > 0; off >>= 1)
        ssum += __shfl_xor_sync(0xffffffffu, ssum, off);
    if ((tid & 31) == 0) sm[tid >> 5] = ssum;
    __syncthreads();
    if (tid == 0) {
        float tt = 0.f;
#pragma unroll
        for (int k = 0; k < 8; k++) tt += sm[k];
        bcast = 1.0f / tt;
    }
    __syncthreads();
    float invs = bcast;
    v.x *= invs; v.y *= invs; v.z *= invs; v.w *= invs;
    *(float4*)(row + tid * 4) = v;
}

__global__ void finalize_kernel(float* __restrict__ out, int out_size)
{
    if (threadIdx.x == 0 && out_size > Tn * Hn) {
        float loss = 0.f;
        for (int e = 0; e < En; e++) {
            int a = 0;
            for (int b = 0; b < Bn; b++) a += g_cnt[e * Bn + b];
            loss += ((float)a / (float)Tn) * (g_imp[e] / (float)Tn);
        }
        out[Tn * Hn] = (float)En * loss;
    }
}

// ---------------- fp16 mma.sync GEMM: 128x128 tile, 8 warps, warp 64x32 ----------------
enum { KK = 0, KV = 1, KQ = 2, KF1 = 3, KF2 = 4, KSC = 5, KPV = 6, KO = 7 };

__device__ __forceinline__ void mma_f16_16x8x16(float* c, const uint32_t* a, const uint32_t* b) {
    asm volatile(
        "mma.sync.aligned.m16n8k16.row.col.f32.f16.f16.f32 "
        "{%0,%1,%2,%3}, {%4,%5,%6,%7}, {%8,%9}, {%0,%1,%2,%3};"
        : "+f"(c[0]), "+f"(c[1]), "+f"(c[2]), "+f"(c[3])
        : "r"(a[0]), "r"(a[1]), "r"(a[2]), "r"(a[3]), "r"(b[0]), "r"(b[1]));
}

#define P2 136   // half2 row stride: read/store banks (kp*8 + idx) % 32 -> bijections

template <int KIND>
__global__ __launch_bounds__(256, 2)
void gemm_kernel(const float* __restrict__ Xin, const float* __restrict__ W,
                 const float* __restrict__ bias, float* __restrict__ outp)
{
    constexpr bool BUCKET = (KIND != KK && KIND != KV);
    constexpr bool TRANSB = (KIND == KSC);
    constexpr int  KDIM = (KIND == KF2) ? Fn : (KIND == KPV ? Sn : Hn);
    constexpr int  LDB  = (KIND == KF1) ? Fn : Hn;

    const int tid  = threadIdx.x;
    const int wid  = tid >> 5;
    const int lane = tid & 31;
    const int z = blockIdx.z;
    int e, bb = 0, M;
    if (BUCKET) {
        e = z >> 2; bb = z & 3;
        M = g_cnt[z];
        if ((int)(blockIdx.x * 128) >= M) return;
    } else {
        e = z; M = Tn;
    }

    const float* Bptr;
    if      (KIND == KK || KIND == KV || KIND == KQ || KIND == KO) Bptr = W + (size_t)e * Hn * Hn;
    else if (KIND == KF1) Bptr = W + (size_t)e * Hn * Fn;
    else if (KIND == KF2) Bptr = W + (size_t)e * Fn * Hn;
    else if (KIND == KSC) Bptr = g_K + ((size_t)e * Tn + (size_t)bb * Sn) * Hn;
    else                  Bptr = g_V + ((size_t)e * Tn + (size_t)bb * Sn) * Hn;  // KPV

    const int row0 = blockIdx.x * 128;
    const int col0 = blockIdx.y * 128;

    // ---- A loader: m = tid&127, k-group = tid>>7 (8 halfs each) ----
    const int am  = tid & 127;
    const int akg = tid >> 7;              // 0/1 -> k offset 8*akg
    const int grow = row0 + am;
    const bool aval = grow < M;
    const float* aRow = nullptr;
    if (aval) {
        if      (KIND == KQ || KIND == KF1)  aRow = Xin + (size_t)g_tok[z * CAPn + grow] * Hn;
        else if (KIND == KK || KIND == KV)   aRow = Xin + (size_t)grow * Hn;
        else if (KIND == KF2)                aRow = g_h1 + ((size_t)z * CAPn + grow) * Fn;
        else if (KIND == KSC)                aRow = g_q  + ((size_t)z * CAPn + grow) * Hn;
        else if (KIND == KPV)                aRow = g_sc + ((size_t)z * CAPn + grow) * Sn;
        else                                 aRow = g_a  + ((size_t)z * CAPn + grow) * Hn;  // KO
    }
    // B normal loader: kp = tid>>5 (0..7), n4 = (tid&31)*4
    const int bkp = tid >> 5;
    const int bn4 = (tid & 31) * 4;
    // B trans loader: n = tid&127, k-group = tid>>7  (same as A)

    __shared__ __align__(16) __half2 As2[8 * P2];
    __shared__ __align__(16) __half2 Bs2[8 * P2];

    float acc[4][4][4];
#pragma unroll
    for (int i = 0; i < 4; i++)
#pragma unroll
        for (int j = 0; j < 4; j++)
#pragma unroll
            for (int k = 0; k < 4; k++) acc[i][j][k] = 0.f;

    const int wm  = (wid >> 2) * 64;   // warp m offset
    const int wn  = (wid & 3) * 32;    // warp n offset
    const int grp = lane >> 2;
    const int tg  = lane & 3;

    // ---- prefetch chunk 0 ----
    float4 pa0 = make_float4(0.f,0.f,0.f,0.f), pa1 = pa0, pb0, pb1;
    if (aval) {
        pa0 = *(const float4*)(aRow + akg * 8);
        pa1 = *(const float4*)(aRow + akg * 8 + 4);
    }
    if (!TRANSB) {
        const float* bs0 = Bptr + (size_t)(2 * bkp)     * LDB + col0 + bn4;
        const float* bs1 = Bptr + (size_t)(2 * bkp + 1) * LDB + col0 + bn4;
        pb0 = *(const float4*)bs0;
        pb1 = *(const float4*)bs1;
    } else {
        const float* bs = Bptr + (size_t)(col0 + am) * LDB + akg * 8;
        pb0 = *(const float4*)bs;
        pb1 = *(const float4*)(bs + 4);
    }

    for (int kt = 0; kt < KDIM; kt += 16) {
        // ---- store prefetched tile as half2 k-pairs ----
        {
            As2[(akg * 4 + 0) * P2 + am] = __floats2half2_rn(pa0.x, pa0.y);
            As2[(akg * 4 + 1) * P2 + am] = __floats2half2_rn(pa0.z, pa0.w);
            As2[(akg * 4 + 2) * P2 + am] = __floats2half2_rn(pa1.x, pa1.y);
            As2[(akg * 4 + 3) * P2 + am] = __floats2half2_rn(pa1.z, pa1.w);
        }
        if (!TRANSB) {
            __half2 h[4];
            h[0] = __floats2half2_rn(pb0.x, pb1.x);
            h[1] = __floats2half2_rn(pb0.y, pb1.y);
            h[2] = __floats2half2_rn(pb0.z, pb1.z);
            h[3] = __floats2half2_rn(pb0.w, pb1.w);
            *(uint4*)&Bs2[bkp * P2 + bn4] = *(uint4*)h;
        } else {
            Bs2[(akg * 4 + 0) * P2 + am] = __floats2half2_rn(pb0.x, pb0.y);
            Bs2[(akg * 4 + 1) * P2 + am] = __floats2half2_rn(pb0.z, pb0.w);
            Bs2[(akg * 4 + 2) * P2 + am] = __floats2half2_rn(pb1.x, pb1.y);
            Bs2[(akg * 4 + 3) * P2 + am] = __floats2half2_rn(pb1.z, pb1.w);
        }
        __syncthreads();

        // ---- prefetch next chunk ----
        if (kt + 16 < KDIM) {
            if (aval) {
                pa0 = *(const float4*)(aRow + kt + 16 + akg * 8);
                pa1 = *(const float4*)(aRow + kt + 16 + akg * 8 + 4);
            }
            if (!TRANSB) {
                const float* bs0 = Bptr + (size_t)(kt + 16 + 2 * bkp)     * LDB + col0 + bn4;
                const float* bs1 = Bptr + (size_t)(kt + 16 + 2 * bkp + 1) * LDB + col0 + bn4;
                pb0 = *(const float4*)bs0;
                pb1 = *(const float4*)bs1;
            } else {
                const float* bs = Bptr + (size_t)(col0 + am) * LDB + kt + 16 + akg * 8;
                pb0 = *(const float4*)bs;
                pb1 = *(const float4*)(bs + 4);
            }
        }

        // ---- compute one k16 step ----
        {
            uint32_t af[4][4], bf[4][2];
#pragma unroll
            for (int mt = 0; mt < 4; mt++) {
                const int m = wm + mt * 16 + grp;
                af[mt][0] = *(const uint32_t*)&As2[tg * P2 + m];
                af[mt][1] = *(const uint32_t*)&As2[tg * P2 + m + 8];
                af[mt][2] = *(const uint32_t*)&As2[(tg + 4) * P2 + m];
                af[mt][3] = *(const uint32_t*)&As2[(tg + 4) * P2 + m + 8];
            }
#pragma unroll
            for (int nt = 0; nt < 4; nt++) {
                const int n = wn + nt * 8 + grp;
                bf[nt][0] = *(const uint32_t*)&Bs2[tg * P2 + n];
                bf[nt][1] = *(const uint32_t*)&Bs2[(tg + 4) * P2 + n];
            }
#pragma unroll
            for (int mt = 0; mt < 4; mt++)
#pragma unroll
                for (int nt = 0; nt < 4; nt++)
                    mma_f16_16x8x16(acc[mt][nt], af[mt], bf[nt]);
        }
        __syncthreads();
    }

    // ---------------- epilogue ----------------
    // lane owns rows: row0+wm+mt*16+grp (+8), cols: col0+wn+nt*8+tg*2 (+1)
#pragma unroll
    for (int mt = 0; mt < 4; mt++) {
#pragma unroll
        for (int half = 0; half < 2; half++) {
            const int r = row0 + wm + mt * 16 + grp + half * 8;
            if (BUCKET && r >= M) continue;

            if (KIND == KK || KIND == KV) {
                float* C = (KIND == KK ? g_K : g_V) + (size_t)e * Tn * Hn + (size_t)r * Hn;
                const float* bp = bias + (size_t)e * Hn;
#pragma unroll
                for (int nt = 0; nt < 4; nt++) {
                    const int c = col0 + wn + nt * 8 + tg * 2;
                    float2 bv = *(const float2*)(bp + c);
                    float2 v = make_float2(acc[mt][nt][half*2]   + bv.x,
                                           acc[mt][nt][half*2+1] + bv.y);
                    *(float2*)(C + c) = v;
                }
            } else if (KIND == KQ) {
                float* C = g_q + ((size_t)z * CAPn + r) * Hn;
                const float* bp = bias + (size_t)e * Hn;
#pragma unroll
                for (int nt = 0; nt < 4; nt++) {
                    const int c = col0 + wn + nt * 8 + tg * 2;
                    float2 bv = *(const float2*)(bp + c);
                    float2 v = make_float2(acc[mt][nt][half*2]   + bv.x,
                                           acc[mt][nt][half*2+1] + bv.y);
                    *(float2*)(C + c) = v;
                }
            } else if (KIND == KF1) {
                float* C = g_h1 + ((size_t)z * CAPn + r) * Fn;
                const float* bp = bias + (size_t)e * Fn;
#pragma unroll
                for (int nt = 0; nt < 4; nt++) {
                    const int c = col0 + wn + nt * 8 + tg * 2;
                    float2 bv = *(const float2*)(bp + c);
                    float t0 = acc[mt][nt][half*2]   + bv.x;
                    float t1 = acc[mt][nt][half*2+1] + bv.y;
                    float2 v;
                    v.x = 0.5f * t0 * (1.0f + erff(t0 * 0.70710678118654752f));
                    v.y = 0.5f * t1 * (1.0f + erff(t1 * 0.70710678118654752f));
                    *(float2*)(C + c) = v;
                }
            } else if (KIND == KF2) {
                float* C = g_h2 + ((size_t)z * CAPn + r) * Hn;
                const float* bp = bias + (size_t)e * Hn;
#pragma unroll
                for (int nt = 0; nt < 4; nt++) {
                    const int c = col0 + wn + nt * 8 + tg * 2;
                    float2 bv = *(const float2*)(bp + c);
                    float2 v = make_float2(acc[mt][nt][half*2]   + bv.x,
                                           acc[mt][nt][half*2+1] + bv.y);
                    *(float2*)(C + c) = v;
                }
            } else if (KIND == KSC) {
                const float scl = 0.044194173824159216f;  // 1/sqrt(512)
                float* C = g_sc + ((size_t)z * CAPn + r) * Sn;
#pragma unroll
                for (int nt = 0; nt < 4; nt++) {
                    const int c = col0 + wn + nt * 8 + tg * 2;
                    float2 v = make_float2(acc[mt][nt][half*2]   * scl,
                                           acc[mt][nt][half*2+1] * scl);
                    *(float2*)(C + c) = v;
                }
            } else if (KIND == KPV) {
                float* C = g_a + ((size_t)z * CAPn + r) * Hn;
#pragma unroll
                for (int nt = 0; nt < 4; nt++) {
                    const int c = col0 + wn + nt * 8 + tg * 2;
                    float2 v = make_float2(acc[mt][nt][half*2],
                                           acc[mt][nt][half*2+1]);
                    *(float2*)(C + c) = v;
                }
            } else {  // KO
                const int tok = g_tok[z * CAPn + r];
                const float wt = g_wt[z * CAPn + r];
                const float* bp = bias + (size_t)e * Hn;
                const float* h2 = g_h2 + ((size_t)z * CAPn + r) * Hn;
                float* od = outp + (size_t)tok * Hn;
#pragma unroll
                for (int nt = 0; nt < 4; nt++) {
                    const int c = col0 + wn + nt * 8 + tg * 2;
                    float v0 = acc[mt][nt][half*2]   + bp[c]   + h2[c];
                    float v1 = acc[mt][nt][half*2+1] + bp[c+1] + h2[c+1];
                    atomicAdd(od + c,     wt * v0);
                    atomicAdd(od + c + 1, wt * v1);
                }
            }
        }
    }
}

// ---------------- launch ----------------
extern "C" void kernel_launch(void* const* d_in, const int* in_sizes, int n_in,
                              void* d_out, int out_size)
{
    const float* x    = (const float*)d_in[0];
    const float* Wg   = (const float*)d_in[1];
    const float* bg   = (const float*)d_in[2];
    const float* fc1w = (const float*)d_in[3];
    const float* fc1b = (const float*)d_in[4];
    const float* fc2w = (const float*)d_in[5];
    const float* fc2b = (const float*)d_in[6];
    const float* qw   = (const float*)d_in[7];
    const float* qb   = (const float*)d_in[8];
    const float* kw   = (const float*)d_in[9];
    const float* kb   = (const float*)d_in[10];
    const float* vw   = (const float*)d_in[11];
    const float* vb   = (const float*)d_in[12];
    const float* ow   = (const float*)d_in[13];
    const float* ob   = (const float*)d_in[14];
    float* out = (float*)d_out;

    reset_kernel<<<1, 64>>>();
    zero_kernel<<<(out_size + 255) / 256, 256>>>(out, out_size);
    router_kernel<<<Tn / 8, 256>>>(x, Wg, bg);

    dim3 gkv(Tn / 128, Hn / 128, En);
    gemm_kernel<KK><<<gkv, 256>>>(x, kw, kb, nullptr);
    gemm_kernel<KV><<<gkv, 256>>>(x, vw, vb, nullptr);

    dim3 gq(CAPn / 128, Hn / 128, NBUCK);
    gemm_kernel<KQ><<<gq, 256>>>(x, qw, qb, nullptr);

    dim3 gf1(CAPn / 128, Fn / 128, NBUCK);
    gemm_kernel<KF1><<<gf1, 256>>>(x, fc1w, fc1b, nullptr);

    dim3 gf2(CAPn / 128, Hn / 128, NBUCK);
    gemm_kernel<KF2><<<gf2, 256>>>(nullptr, fc2w, fc2b, nullptr);

    dim3 gsc(CAPn / 128, Sn / 128, NBUCK);
    gemm_kernel<KSC><<<gsc, 256>>>(nullptr, nullptr, nullptr, nullptr);

    softmax_kernel<<<NBUCK * CAPn, 256>>>();

    dim3 gpv(CAPn / 128, Hn / 128, NBUCK);
    gemm_kernel<KPV><<<gpv, 256>>>(nullptr, nullptr, nullptr, nullptr);

    dim3 go(CAPn / 128, Hn / 128, NBUCK);
    gemm_kernel<KO><<<go, 256>>>(nullptr, ow, ob, out);

    finalize_kernel<<<1, 32>>>(out, out_size);
}

// round 6
// speedup vs baseline: 1.4376x; 1.1740x over previous
#include <cuda_runtime.h>
#include <cuda_fp16.h>
#include <math.h>
#include <stdint.h>

// Problem constants
#define Bn 4
#define Sn 1024
#define Tn 4096          // Bn*Sn tokens
#define Hn 512
#define En 8
#define Fn 2048
#define NBUCK 32         // En*Bn  (expert, batch) buckets
#define CAPn 1024        // max tokens per bucket = Sn

// ---------------- scratch (__device__ globals; no allocation) ----------------
// fp16 operands
__device__ __half g_xh  [(size_t)Tn*Hn];             // x fp16
__device__ __half g_Kh  [(size_t)En*Tn*Hn];          // K proj fp16 [e][t][h] (KSC B, k-major natural)
__device__ __half g_qh  [(size_t)NBUCK*CAPn*Hn];     // q fp16
__device__ __half g_h1h [(size_t)NBUCK*CAPn*Fn];     // gelu(fc1) fp16
__device__ __half g_atth[(size_t)NBUCK*CAPn*Sn];     // attn probs fp16
__device__ __half g_ah  [(size_t)NBUCK*CAPn*Hn];     // attn output fp16
// k-pair interleaved B operands (uint = half2(k, k+1) at fixed n)
__device__ unsigned int g_qwi[(size_t)En*(Hn/2)*Hn];
__device__ unsigned int g_kwi[(size_t)En*(Hn/2)*Hn];
__device__ unsigned int g_vwi[(size_t)En*(Hn/2)*Hn];
__device__ unsigned int g_owi[(size_t)En*(Hn/2)*Hn];
__device__ unsigned int g_f1i[(size_t)En*(Hn/2)*Fn];
__device__ unsigned int g_f2i[(size_t)En*(Fn/2)*Hn];
__device__ unsigned int g_Vi [(size_t)En*(Tn/2)*Hn]; // V interleaved by token pairs
// fp32 buffers
__device__ float g_sc[(size_t)NBUCK*CAPn*Sn];        // scores fp32 (softmax input)
__device__ float g_h2[(size_t)NBUCK*CAPn*Hn];        // ffn out fp32 (added in KO epilogue)
__device__ int   g_cnt[NBUCK];
__device__ int   g_tok[NBUCK*CAPn];
__device__ float g_wt [NBUCK*CAPn];
__device__ float g_imp[En];

__device__ __forceinline__ unsigned int f22u(float a, float b) {
    __half2 h = __floats2half2_rn(a, b);
    return *(unsigned int*)&h;
}

// ---------------- small kernels ----------------
__global__ void reset_kernel() {
    int i = threadIdx.x;
    if (i < NBUCK) g_cnt[i] = 0;
    if (i < En)    g_imp[i] = 0.f;
}

__global__ void zero_kernel(float* __restrict__ out, int n) {
    int i = blockIdx.x * blockDim.x + threadIdx.x;
    if (i < n) out[i] = 0.f;
}

// fp32 -> fp16 elementwise (n multiple of 4)
__global__ void halve_kernel(const float* __restrict__ src, __half* __restrict__ dst, int n) {
    int i = (blockIdx.x * blockDim.x + threadIdx.x) * 4;
    if (i < n) {
        float4 v = *(const float4*)(src + i);
        unsigned int u0 = f22u(v.x, v.y), u1 = f22u(v.z, v.w);
        uint2 o = make_uint2(u0, u1);
        *(uint2*)(dst + i) = o;
    }
}

// fp32 [K][N] -> k-pair interleaved uint [K/2][N] (per expert z)
__global__ void interleave_kernel(const float* __restrict__ src, unsigned int* __restrict__ dst,
                                  int K, int N) {
    int z = blockIdx.z;
    src += (size_t)z * K * N;
    dst += (size_t)z * (K / 2) * N;
    int idx = blockIdx.x * blockDim.x + threadIdx.x;
    int total = (K / 2) * (N / 4);
    if (idx >= total) return;
    int kp = idx / (N / 4);
    int n4 = (idx % (N / 4)) * 4;
    float4 a = *(const float4*)(src + (size_t)(2 * kp) * N + n4);
    float4 b = *(const float4*)(src + (size_t)(2 * kp + 1) * N + n4);
    uint4 o = make_uint4(f22u(a.x, b.x), f22u(a.y, b.y), f22u(a.z, b.z), f22u(a.w, b.w));
    *(uint4*)(dst + (size_t)kp * N + n4) = o;
}

// Router: one warp per token. Exact fp32.
__global__ void router_kernel(const float* __restrict__ x,
                              const float* __restrict__ Wg,
                              const float* __restrict__ bg)
{
    int warp = (blockIdx.x * blockDim.x + threadIdx.x) >> 5;
    int lane = threadIdx.x & 31;
    if (warp >= Tn) return;
    const int t = warp;

    float acc[En];
#pragma unroll
    for (int e = 0; e < En; e++) acc[e] = 0.f;

    for (int h = lane; h < Hn; h += 32) {
        float xv = x[(size_t)t * Hn + h];
        float4 w0 = *(const float4*)(Wg + (size_t)h * En);
        float4 w1 = *(const float4*)(Wg + (size_t)h * En + 4);
        acc[0] += xv * w0.x; acc[1] += xv * w0.y; acc[2] += xv * w0.z; acc[3] += xv * w0.w;
        acc[4] += xv * w1.x; acc[5] += xv * w1.y; acc[6] += xv * w1.z; acc[7] += xv * w1.w;
    }
#pragma unroll
    for (int off = 16; off > 0; off >>= 1) {
#pragma unroll
        for (int e = 0; e < En; e++)
            acc[e] += __shfl_xor_sync(0xffffffffu, acc[e], off);
    }
    if (lane != 0) return;

    float p[En];
    float m = -1e30f;
#pragma unroll
    for (int e = 0; e < En; e++) { p[e] = acc[e] + bg[e]; m = fmaxf(m, p[e]); }
    float s = 0.f;
#pragma unroll
    for (int e = 0; e < En; e++) { p[e] = expf(p[e] - m); s += p[e]; }
    float inv = 1.0f / s;
#pragma unroll
    for (int e = 0; e < En; e++) { p[e] *= inv; atomicAdd(&g_imp[e], p[e]); }

    int i1 = 0;
#pragma unroll
    for (int e = 1; e < En; e++) if (p[e] > p[i1]) i1 = e;
    int i2 = (i1 == 0) ? 1 : 0;
#pragma unroll
    for (int e = 0; e < En; e++) if (e != i1 && p[e] > p[i2]) i2 = e;

    float denom = p[i1] + p[i2];
    int b = t >> 10;
    int bk1 = i1 * Bn + b;
    int pos1 = atomicAdd(&g_cnt[bk1], 1);
    g_tok[bk1 * CAPn + pos1] = t;
    g_wt [bk1 * CAPn + pos1] = p[i1] / denom;
    int bk2 = i2 * Bn + b;
    int pos2 = atomicAdd(&g_cnt[bk2], 1);
    g_tok[bk2 * CAPn + pos2] = t;
    g_wt [bk2 * CAPn + pos2] = p[i2] / denom;
}

// Row softmax: read fp32 scores, write fp16 probs.
__global__ void softmax_kernel()
{
    int bkt = blockIdx.x >> 10;
    int r   = blockIdx.x & (CAPn - 1);
    if (r >= g_cnt[bkt]) return;
    const float* row = g_sc + ((size_t)bkt * CAPn + r) * Sn;
    __half* orow = g_atth + ((size_t)bkt * CAPn + r) * Sn;
    int tid = threadIdx.x;

    float4 v = *(const float4*)(row + tid * 4);
    float m = fmaxf(fmaxf(v.x, v.y), fmaxf(v.z, v.w));

    __shared__ float sm[8];
    __shared__ float bcast;
#pragma unroll
    for (int off = 16; off > 0; off >>= 1)
        m = fmaxf(m, __shfl_xor_sync(0xffffffffu, m, off));
    if ((tid & 31) == 0) sm[tid >> 5] = m;
    __syncthreads();
    if (tid == 0) {
        float mm = sm[0];
#pragma unroll
        for (int k = 1; k < 8; k++) mm = fmaxf(mm, sm[k]);
        bcast = mm;
    }
    __syncthreads();
    float bm = bcast;

    v.x = expf(v.x - bm); v.y = expf(v.y - bm);
    v.z = expf(v.z - bm); v.w = expf(v.w - bm);
    float ssum = v.x + v.y + v.z + v.w;
#pragma unroll
    for (int off = 16; off > 0; off >>= 1)
        ssum += __shfl_xor_sync(0xffffffffu, ssum, off);
    if ((tid & 31) == 0) sm[tid >> 5] = ssum;
    __syncthreads();
    if (tid == 0) {
        float tt = 0.f;
#pragma unroll
        for (int k = 0; k < 8; k++) tt += sm[k];
        bcast = 1.0f / tt;
    }
    __syncthreads();
    float invs = bcast;
    uint2 o = make_uint2(f22u(v.x * invs, v.y * invs), f22u(v.z * invs, v.w * invs));
    *(uint2*)(orow + tid * 4) = o;
}

__global__ void finalize_kernel(float* __restrict__ out, int out_size)
{
    if (threadIdx.x == 0 && out_size > Tn * Hn) {
        float loss = 0.f;
        for (int e = 0; e < En; e++) {
            int a = 0;
            for (int b = 0; b < Bn; b++) a += g_cnt[e * Bn + b];
            loss += ((float)a / (float)Tn) * (g_imp[e] / (float)Tn);
        }
        out[Tn * Hn] = (float)En * loss;
    }
}

// ---------------- fp16 mma.sync GEMM: 128x128 tile, 8 warps 64x32, double-buffered ----------------
enum { KK = 0, KV = 1, KQ = 2, KF1 = 3, KF2 = 4, KSC = 5, KPV = 6, KO = 7 };

__device__ __forceinline__ void mma_f16_16x8x16(float* c, const unsigned int* a, const unsigned int* b) {
    asm volatile(
        "mma.sync.aligned.m16n8k16.row.col.f32.f16.f16.f32 "
        "{%0,%1,%2,%3}, {%4,%5,%6,%7}, {%8,%9}, {%0,%1,%2,%3};"
        : "+f"(c[0]), "+f"(c[1]), "+f"(c[2]), "+f"(c[3])
        : "r"(a[0]), "r"(a[1]), "r"(a[2]), "r"(a[3]), "r"(b[0]), "r"(b[1]));
}

#define P2 136   // half2/uint row stride -> conflict-free reads & stores

template <int KIND>
__global__ __launch_bounds__(256, 2)
void gemm_kernel(const float* __restrict__ bias, float* __restrict__ outp)
{
    constexpr bool BUCKET = (KIND != KK && KIND != KV);
    constexpr bool TRANSB = (KIND == KSC);
    constexpr int  KDIM = (KIND == KF2) ? Fn : (KIND == KPV ? Sn : Hn);
    constexpr int  LDBu = (KIND == KF1) ? Fn : Hn;   // uints per kp-row (interleaved B)
    constexpr int  NC   = KDIM / 16;

    const int tid  = threadIdx.x;
    const int wid  = tid >> 5;
    const int lane = tid & 31;
    const int z = blockIdx.z;
    int e, bb = 0, M;
    if (BUCKET) {
        e = z >> 2; bb = z & 3;
        M = g_cnt[z];
        if ((int)(blockIdx.x * 128) >= M) return;
    } else {
        e = z; M = Tn;
    }

    const int row0 = blockIdx.x * 128;
    const int col0 = blockIdx.y * 128;

    // ---- B base ----
    const unsigned int* Bu = nullptr;
    const __half* BhT = nullptr;   // TRANSB (KSC): K fp16 [n=t][k=h]
    if      (KIND == KK)  Bu = g_kwi + (size_t)e * (Hn/2) * Hn;
    else if (KIND == KV)  Bu = g_vwi + (size_t)e * (Hn/2) * Hn;
    else if (KIND == KQ)  Bu = g_qwi + (size_t)e * (Hn/2) * Hn;
    else if (KIND == KO)  Bu = g_owi + (size_t)e * (Hn/2) * Hn;
    else if (KIND == KF1) Bu = g_f1i + (size_t)e * (Hn/2) * Fn;
    else if (KIND == KF2) Bu = g_f2i + (size_t)e * (Fn/2) * Hn;
    else if (KIND == KPV) Bu = g_Vi  + ((size_t)e * (Tn/2) + (size_t)bb * (Sn/2)) * Hn;
    else                  BhT = g_Kh + ((size_t)e * Tn + (size_t)bb * Sn) * Hn;  // KSC

    // ---- A loader: row am = tid&127, k-group akg = tid>>7 (8 halfs) ----
    const int am  = tid & 127;
    const int akg = tid >> 7;
    const int grow = row0 + am;
    const bool aval = grow < M;
    const __half* aRow = nullptr;
    if (aval) {
        if      (KIND == KK || KIND == KV)   aRow = g_xh + (size_t)grow * Hn;
        else if (KIND == KQ || KIND == KF1)  aRow = g_xh + (size_t)g_tok[z * CAPn + grow] * Hn;
        else if (KIND == KF2)                aRow = g_h1h  + ((size_t)z * CAPn + grow) * Fn;
        else if (KIND == KSC)                aRow = g_qh   + ((size_t)z * CAPn + grow) * Hn;
        else if (KIND == KPV)                aRow = g_atth + ((size_t)z * CAPn + grow) * Sn;
        else                                 aRow = g_ah   + ((size_t)z * CAPn + grow) * Hn;  // KO
    }
    // B normal loader: kp-row bkp = tid>>5 (0..7), uint4 seg bn4 = (tid&31)*4
    const int bkp = tid >> 5;
    const int bn4 = (tid & 31) * 4;

    __shared__ __align__(16) unsigned int As2[2][8 * P2];
    __shared__ __align__(16) unsigned int Bs2[2][8 * P2];

    float acc[4][4][4];
#pragma unroll
    for (int i = 0; i < 4; i++)
#pragma unroll
        for (int j = 0; j < 4; j++)
#pragma unroll
            for (int k = 0; k < 4; k++) acc[i][j][k] = 0.f;

    const int wm  = (wid >> 2) * 64;
    const int wn  = (wid & 3) * 32;
    const int grp = lane >> 2;
    const int tg  = lane & 3;

    // ---- prefetch chunk 0 ----
    uint4 pa = make_uint4(0, 0, 0, 0), pb;
    if (aval) pa = *(const uint4*)(aRow + akg * 8);
    if (!TRANSB) pb = *(const uint4*)(Bu + (size_t)bkp * LDBu + col0 + bn4);
    else         pb = *(const uint4*)(BhT + (size_t)(col0 + am) * Hn + akg * 8);

    for (int c = 0; c < NC; c++) {
        unsigned int* As = As2[c & 1];
        unsigned int* Bs = Bs2[c & 1];
        // stores (k-pair rows kp = akg*4 + j)
        As[(akg * 4 + 0) * P2 + am] = pa.x;
        As[(akg * 4 + 1) * P2 + am] = pa.y;
        As[(akg * 4 + 2) * P2 + am] = pa.z;
        As[(akg * 4 + 3) * P2 + am] = pa.w;
        if (!TRANSB) {
            *(uint4*)&Bs[bkp * P2 + bn4] = pb;
        } else {
            Bs[(akg * 4 + 0) * P2 + am] = pb.x;
            Bs[(akg * 4 + 1) * P2 + am] = pb.y;
            Bs[(akg * 4 + 2) * P2 + am] = pb.z;
            Bs[(akg * 4 + 3) * P2 + am] = pb.w;
        }
        __syncthreads();

        // prefetch next chunk (overlaps MMA below)
        if (c + 1 < NC) {
            const int kt = (c + 1) * 16;
            pa = make_uint4(0, 0, 0, 0);
            if (aval) pa = *(const uint4*)(aRow + kt + akg * 8);
            if (!TRANSB) pb = *(const uint4*)(Bu + (size_t)(kt / 2 + bkp) * LDBu + col0 + bn4);
            else         pb = *(const uint4*)(BhT + (size_t)(col0 + am) * Hn + kt + akg * 8);
        }

        // compute one k16 step
        {
            unsigned int af[4][4], bf[4][2];
#pragma unroll
            for (int mt = 0; mt < 4; mt++) {
                const int m = wm + mt * 16 + grp;
                af[mt][0] = As[tg * P2 + m];
                af[mt][1] = As[tg * P2 + m + 8];
                af[mt][2] = As[(tg + 4) * P2 + m];
                af[mt][3] = As[(tg + 4) * P2 + m + 8];
            }
#pragma unroll
            for (int nt = 0; nt < 4; nt++) {
                const int n = wn + nt * 8 + grp;
                bf[nt][0] = Bs[tg * P2 + n];
                bf[nt][1] = Bs[(tg + 4) * P2 + n];
            }
#pragma unroll
            for (int mt = 0; mt < 4; mt++)
#pragma unroll
                for (int nt = 0; nt < 4; nt++)
                    mma_f16_16x8x16(acc[mt][nt], af[mt], bf[nt]);
        }
        // single barrier per chunk: next iter stores target the other buffer
    }

    // ---------------- epilogue ----------------
#pragma unroll
    for (int mt = 0; mt < 4; mt++) {
#pragma unroll
        for (int half = 0; half < 2; half++) {
            const int r = row0 + wm + mt * 16 + grp + half * 8;
            if (BUCKET && r >= M) continue;

            if (KIND == KK) {
                __half* C = g_Kh + ((size_t)e * Tn + r) * Hn;
                const float* bp = bias + (size_t)e * Hn;
#pragma unroll
                for (int nt = 0; nt < 4; nt++) {
                    const int c = col0 + wn + nt * 8 + tg * 2;
                    float2 bv = *(const float2*)(bp + c);
                    unsigned int u = f22u(acc[mt][nt][half*2] + bv.x, acc[mt][nt][half*2+1] + bv.y);
                    *(unsigned int*)(C + c) = u;
                }
            } else if (KIND == KV) {
                // interleaved V: half index = 2*((e*Tn/2 + r/2)*Hn + c) + (r&1)
                __half* Vh = (__half*)g_Vi;
                const float* bp = bias + (size_t)e * Hn;
                size_t base = 2 * (((size_t)e * (Tn/2) + (r >> 1)) * Hn);
                int par = r & 1;
#pragma unroll
                for (int nt = 0; nt < 4; nt++) {
                    const int c = col0 + wn + nt * 8 + tg * 2;
                    float2 bv = *(const float2*)(bp + c);
                    Vh[base + 2 * c + par]     = __float2half_rn(acc[mt][nt][half*2]   + bv.x);
                    Vh[base + 2 * (c+1) + par] = __float2half_rn(acc[mt][nt][half*2+1] + bv.y);
                }
            } else if (KIND == KQ) {
                __half* C = g_qh + ((size_t)z * CAPn + r) * Hn;
                const float* bp = bias + (size_t)e * Hn;
#pragma unroll
                for (int nt = 0; nt < 4; nt++) {
                    const int c = col0 + wn + nt * 8 + tg * 2;
                    float2 bv = *(const float2*)(bp + c);
                    unsigned int u = f22u(acc[mt][nt][half*2] + bv.x, acc[mt][nt][half*2+1] + bv.y);
                    *(unsigned int*)(C + c) = u;
                }
            } else if (KIND == KF1) {
                __half* C = g_h1h + ((size_t)z * CAPn + r) * Fn;
                const float* bp = bias + (size_t)e * Fn;
#pragma unroll
                for (int nt = 0; nt < 4; nt++) {
                    const int c = col0 + wn + nt * 8 + tg * 2;
                    float2 bv = *(const float2*)(bp + c);
                    float t0 = acc[mt][nt][half*2]   + bv.x;
                    float t1 = acc[mt][nt][half*2+1] + bv.y;
                    t0 = 0.5f * t0 * (1.0f + erff(t0 * 0.70710678118654752f));
                    t1 = 0.5f * t1 * (1.0f + erff(t1 * 0.70710678118654752f));
                    *(unsigned int*)(C + c) = f22u(t0, t1);
                }
            } else if (KIND == KF2) {
                float* C = g_h2 + ((size_t)z * CAPn + r) * Hn;
                const float* bp = bias + (size_t)e * Hn;
#pragma unroll
                for (int nt = 0; nt < 4; nt++) {
                    const int c = col0 + wn + nt * 8 + tg * 2;
                    float2 bv = *(const float2*)(bp + c);
                    float2 v = make_float2(acc[mt][nt][half*2]   + bv.x,
                                           acc[mt][nt][half*2+1] + bv.y);
                    *(float2*)(C + c) = v;
                }
            } else if (KIND == KSC) {
                const float scl = 0.044194173824159216f;  // 1/sqrt(512)
                float* C = g_sc + ((size_t)z * CAPn + r) * Sn;
#pragma unroll
                for (int nt = 0; nt < 4; nt++) {
                    const int c = col0 + wn + nt * 8 + tg * 2;
                    float2 v = make_float2(acc[mt][nt][half*2]   * scl,
                                           acc[mt][nt][half*2+1] * scl);
                    *(float2*)(C + c) = v;
                }
            } else if (KIND == KPV) {
                __half* C = g_ah + ((size_t)z * CAPn + r) * Hn;
#pragma unroll
                for (int nt = 0; nt < 4; nt++) {
                    const int c = col0 + wn + nt * 8 + tg * 2;
                    *(unsigned int*)(C + c) = f22u(acc[mt][nt][half*2], acc[mt][nt][half*2+1]);
                }
            } else {  // KO
                const int tok = g_tok[z * CAPn + r];
                const float wt = g_wt[z * CAPn + r];
                const float* bp = bias + (size_t)e * Hn;
                const float* h2 = g_h2 + ((size_t)z * CAPn + r) * Hn;
                float* od = outp + (size_t)tok * Hn;
#pragma unroll
                for (int nt = 0; nt < 4; nt++) {
                    const int c = col0 + wn + nt * 8 + tg * 2;
                    float v0 = acc[mt][nt][half*2]   + bp[c]   + h2[c];
                    float v1 = acc[mt][nt][half*2+1] + bp[c+1] + h2[c+1];
                    atomicAdd(od + c,     wt * v0);
                    atomicAdd(od + c + 1, wt * v1);
                }
            }
        }
    }
}

// ---------------- launch ----------------
extern "C" void kernel_launch(void* const* d_in, const int* in_sizes, int n_in,
                              void* d_out, int out_size)
{
    const float* x    = (const float*)d_in[0];
    const float* Wg   = (const float*)d_in[1];
    const float* bg   = (const float*)d_in[2];
    const float* fc1w = (const float*)d_in[3];
    const float* fc1b = (const float*)d_in[4];
    const float* fc2w = (const float*)d_in[5];
    const float* fc2b = (const float*)d_in[6];
    const float* qw   = (const float*)d_in[7];
    const float* qb   = (const float*)d_in[8];
    const float* kw   = (const float*)d_in[9];
    const float* kb   = (const float*)d_in[10];
    const float* vw   = (const float*)d_in[11];
    const float* vb   = (const float*)d_in[12];
    const float* ow   = (const float*)d_in[13];
    const float* ob   = (const float*)d_in[14];
    float* out = (float*)d_out;

    __half* dxh;        cudaGetSymbolAddress((void**)&dxh,  g_xh);
    unsigned int* dqwi; cudaGetSymbolAddress((void**)&dqwi, g_qwi);
    unsigned int* dkwi; cudaGetSymbolAddress((void**)&dkwi, g_kwi);
    unsigned int* dvwi; cudaGetSymbolAddress((void**)&dvwi, g_vwi);
    unsigned int* dowi; cudaGetSymbolAddress((void**)&dowi, g_owi);
    unsigned int* df1i; cudaGetSymbolAddress((void**)&df1i, g_f1i);
    unsigned int* df2i; cudaGetSymbolAddress((void**)&df2i, g_f2i);

    reset_kernel<<<1, 64>>>();
    zero_kernel<<<(out_size + 255) / 256, 256>>>(out, out_size);

    // conversions
    halve_kernel<<<(Tn * Hn / 4 + 255) / 256, 256>>>(x, dxh, Tn * Hn);
    {
        int itemsW = (Hn / 2) * (Hn / 4);
        interleave_kernel<<<dim3((itemsW + 255) / 256, 1, En), 256>>>(qw, dqwi, Hn, Hn);
        interleave_kernel<<<dim3((itemsW + 255) / 256, 1, En), 256>>>(kw, dkwi, Hn, Hn);
        interleave_kernel<<<dim3((itemsW + 255) / 256, 1, En), 256>>>(vw, dvwi, Hn, Hn);
        interleave_kernel<<<dim3((itemsW + 255) / 256, 1, En), 256>>>(ow, dowi, Hn, Hn);
        int items1 = (Hn / 2) * (Fn / 4);
        interleave_kernel<<<dim3((items1 + 255) / 256, 1, En), 256>>>(fc1w, df1i, Hn, Fn);
        int items2 = (Fn / 2) * (Hn / 4);
        interleave_kernel<<<dim3((items2 + 255) / 256, 1, En), 256>>>(fc2w, df2i, Fn, Hn);
    }

    router_kernel<<<Tn / 8, 256>>>(x, Wg, bg);

    dim3 gkv(Tn / 128, Hn / 128, En);
    gemm_kernel<KK><<<gkv, 256>>>(kb, nullptr);
    gemm_kernel<KV><<<gkv, 256>>>(vb, nullptr);

    gemm_kernel<KQ ><<<dim3(CAPn / 128, Hn / 128, NBUCK), 256>>>(qb, nullptr);
    gemm_kernel<KF1><<<dim3(CAPn / 128, Fn / 128, NBUCK), 256>>>(fc1b, nullptr);
    gemm_kernel<KF2><<<dim3(CAPn / 128, Hn / 128, NBUCK), 256>>>(fc2b, nullptr);
    gemm_kernel<KSC><<<dim3(CAPn / 128, Sn / 128, NBUCK), 256>>>(nullptr, nullptr);

    softmax_kernel<<<NBUCK * CAPn, 256>>>();

    gemm_kernel<KPV><<<dim3(CAPn / 128, Hn / 128, NBUCK), 256>>>(nullptr, nullptr);
    gemm_kernel<KO ><<<dim3(CAPn / 128, Hn / 128, NBUCK), 256>>>(ob, out);

    finalize_kernel<<<1, 32>>>(out, out_size);
}

// round 7
// speedup vs baseline: 2.0412x; 1.4199x over previous
#include <cuda_runtime.h>
#include <cuda_fp16.h>
#include <math.h>
#include <stdint.h>

// Problem constants
#define Bn 4
#define Sn 1024
#define Tn 4096          // Bn*Sn tokens
#define Hn 512
#define En 8
#define Fn 2048
#define NBUCK 32         // En*Bn  (expert, batch) buckets
#define CAPn 1024        // max tokens per bucket = Sn

// ---------------- scratch (__device__ globals; no allocation) ----------------
// fp16 activations
__device__ __half g_xh  [(size_t)Tn*Hn];             // x fp16
__device__ __half g_Kh  [(size_t)En*Tn*Hn];          // K proj fp16 [e][t][h]
__device__ __half g_Vth [(size_t)En*Hn*Tn];          // V proj fp16 TRANSPOSED [e][h][t]
__device__ __half g_qh  [(size_t)NBUCK*CAPn*Hn];     // q fp16
__device__ __half g_h1h [(size_t)NBUCK*CAPn*Fn];     // gelu(fc1) fp16
__device__ __half g_atth[(size_t)NBUCK*CAPn*Sn];     // attn probs fp16
__device__ __half g_ah  [(size_t)NBUCK*CAPn*Hn];     // attn output fp16
// fp16 transposed weights [E][N][K]
__device__ __half g_qwT[(size_t)En*Hn*Hn];
__device__ __half g_kwT[(size_t)En*Hn*Hn];
__device__ __half g_vwT[(size_t)En*Hn*Hn];
__device__ __half g_owT[(size_t)En*Hn*Hn];
__device__ __half g_f1T[(size_t)En*Fn*Hn];           // [e][F][H]
__device__ __half g_f2T[(size_t)En*Hn*Fn];           // [e][H][F]
// fp32 buffers
__device__ float g_sc[(size_t)NBUCK*CAPn*Sn];        // scores fp32 (softmax input)
__device__ float g_h2[(size_t)NBUCK*CAPn*Hn];        // ffn out fp32
__device__ int   g_cnt[NBUCK];
__device__ int   g_tok[NBUCK*CAPn];
__device__ float g_wt [NBUCK*CAPn];
__device__ float g_imp[En];

__device__ __forceinline__ unsigned int f22u(float a, float b) {
    __half2 h = __floats2half2_rn(a, b);
    return *(unsigned int*)&h;
}
__device__ __forceinline__ uint32_t smem_u32(const void* p) {
    uint32_t a;
    asm("{ .reg .u64 t; cvta.to.shared.u64 t, %1; cvt.u32.u64 %0, t; }" : "=r"(a) : "l"(p));
    return a;
}

// ---------------- small kernels ----------------
__global__ void reset_kernel() {
    int i = threadIdx.x;
    if (i < NBUCK) g_cnt[i] = 0;
    if (i < En)    g_imp[i] = 0.f;
}

__global__ void zero_kernel(float* __restrict__ out, int n) {
    int i = blockIdx.x * blockDim.x + threadIdx.x;
    if (i < n) out[i] = 0.f;
}

// fp32 -> fp16 elementwise (n multiple of 4)
__global__ void halve_kernel(const float* __restrict__ src, __half* __restrict__ dst, int n) {
    int i = (blockIdx.x * blockDim.x + threadIdx.x) * 4;
    if (i < n) {
        float4 v = *(const float4*)(src + i);
        uint2 o = make_uint2(f22u(v.x, v.y), f22u(v.z, v.w));
        *(uint2*)(dst + i) = o;
    }
}

// fp32 [E][R][C] -> fp16 [E][C][R]
__global__ void transpose_h_kernel(const float* __restrict__ in, __half* __restrict__ out,
                                   int R, int C)
{
    __shared__ float t[32][33];
    int e = blockIdx.z;
    const float* src = in + (size_t)e * R * C;
    __half* dst = out + (size_t)e * R * C;
    int c0 = blockIdx.x * 32, r0 = blockIdx.y * 32;
    int x = threadIdx.x, y = threadIdx.y;   // (32, 8)
#pragma unroll
    for (int i = 0; i < 32; i += 8)
        t[y + i][x] = src[(size_t)(r0 + y + i) * C + c0 + x];
    __syncthreads();
#pragma unroll
    for (int i = 0; i < 32; i += 8)
        dst[(size_t)(c0 + y + i) * R + r0 + x] = __float2half_rn(t[x][y + i]);
}

// Router: one warp per token. Exact fp32.
__global__ void router_kernel(const float* __restrict__ x,
                              const float* __restrict__ Wg,
                              const float* __restrict__ bg)
{
    int warp = (blockIdx.x * blockDim.x + threadIdx.x) >> 5;
    int lane = threadIdx.x & 31;
    if (warp >= Tn) return;
    const int t = warp;

    float acc[En];
#pragma unroll
    for (int e = 0; e < En; e++) acc[e] = 0.f;

    for (int h = lane; h < Hn; h += 32) {
        float xv = x[(size_t)t * Hn + h];
        float4 w0 = *(const float4*)(Wg + (size_t)h * En);
        float4 w1 = *(const float4*)(Wg + (size_t)h * En + 4);
        acc[0] += xv * w0.x; acc[1] += xv * w0.y; acc[2] += xv * w0.z; acc[3] += xv * w0.w;
        acc[4] += xv * w1.x; acc[5] += xv * w1.y; acc[6] += xv * w1.z; acc[7] += xv * w1.w;
    }
#pragma unroll
    for (int off = 16; off > 0; off >>= 1) {
#pragma unroll
        for (int e = 0; e < En; e++)
            acc[e] += __shfl_xor_sync(0xffffffffu, acc[e], off);
    }
    if (lane != 0) return;

    float p[En];
    float m = -1e30f;
#pragma unroll
    for (int e = 0; e < En; e++) { p[e] = acc[e] + bg[e]; m = fmaxf(m, p[e]); }
    float s = 0.f;
#pragma unroll
    for (int e = 0; e < En; e++) { p[e] = expf(p[e] - m); s += p[e]; }
    float inv = 1.0f / s;
#pragma unroll
    for (int e = 0; e < En; e++) { p[e] *= inv; atomicAdd(&g_imp[e], p[e]); }

    int i1 = 0;
#pragma unroll
    for (int e = 1; e < En; e++) if (p[e] > p[i1]) i1 = e;
    int i2 = (i1 == 0) ? 1 : 0;
#pragma unroll
    for (int e = 0; e < En; e++) if (e != i1 && p[e] > p[i2]) i2 = e;

    float denom = p[i1] + p[i2];
    int b = t >> 10;
    int bk1 = i1 * Bn + b;
    int pos1 = atomicAdd(&g_cnt[bk1], 1);
    g_tok[bk1 * CAPn + pos1] = t;
    g_wt [bk1 * CAPn + pos1] = p[i1] / denom;
    int bk2 = i2 * Bn + b;
    int pos2 = atomicAdd(&g_cnt[bk2], 1);
    g_tok[bk2 * CAPn + pos2] = t;
    g_wt [bk2 * CAPn + pos2] = p[i2] / denom;
}

// Row softmax: read fp32 scores, write fp16 probs.
__global__ void softmax_kernel()
{
    int bkt = blockIdx.x >> 10;
    int r   = blockIdx.x & (CAPn - 1);
    if (r >= g_cnt[bkt]) return;
    const float* row = g_sc + ((size_t)bkt * CAPn + r) * Sn;
    __half* orow = g_atth + ((size_t)bkt * CAPn + r) * Sn;
    int tid = threadIdx.x;

    float4 v = *(const float4*)(row + tid * 4);
    float m = fmaxf(fmaxf(v.x, v.y), fmaxf(v.z, v.w));

    __shared__ float sm[8];
    __shared__ float bcast;
#pragma unroll
    for (int off = 16; off > 0; off >>= 1)
        m = fmaxf(m, __shfl_xor_sync(0xffffffffu, m, off));
    if ((tid & 31) == 0) sm[tid >> 5] = m;
    __syncthreads();
    if (tid == 0) {
        float mm = sm[0];
#pragma unroll
        for (int k = 1; k < 8; k++) mm = fmaxf(mm, sm[k]);
        bcast = mm;
    }
    __syncthreads();
    float bm = bcast;

    v.x = expf(v.x - bm); v.y = expf(v.y - bm);
    v.z = expf(v.z - bm); v.w = expf(v.w - bm);
    float ssum = v.x + v.y + v.z + v.w;
#pragma unroll
    for (int off = 16; off > 0; off >>= 1)
        ssum += __shfl_xor_sync(0xffffffffu, ssum, off);
    if ((tid & 31) == 0) sm[tid >> 5] = ssum;
    __syncthreads();
    if (tid == 0) {
        float tt = 0.f;
#pragma unroll
        for (int k = 0; k < 8; k++) tt += sm[k];
        bcast = 1.0f / tt;
    }
    __syncthreads();
    float invs = bcast;
    uint2 o = make_uint2(f22u(v.x * invs, v.y * invs), f22u(v.z * invs, v.w * invs));
    *(uint2*)(orow + tid * 4) = o;
}

__global__ void finalize_kernel(float* __restrict__ out, int out_size)
{
    if (threadIdx.x == 0 && out_size > Tn * Hn) {
        float loss = 0.f;
        for (int e = 0; e < En; e++) {
            int a = 0;
            for (int b = 0; b < Bn; b++) a += g_cnt[e * Bn + b];
            loss += ((float)a / (float)Tn) * (g_imp[e] / (float)Tn);
        }
        out[Tn * Hn] = (float)En * loss;
    }
}

// ---------------- fp16 mma GEMM: 128x128 tile, 8 warps 64x32, cp.async + ldmatrix ----------------
enum { KK = 0, KV = 1, KQ = 2, KF1 = 3, KF2 = 4, KSC = 5, KPV = 6, KO = 7 };

__device__ __forceinline__ void mma_f16_16x8x16(float* c, const unsigned int* a, const unsigned int* b) {
    asm volatile(
        "mma.sync.aligned.m16n8k16.row.col.f32.f16.f16.f32 "
        "{%0,%1,%2,%3}, {%4,%5,%6,%7}, {%8,%9}, {%0,%1,%2,%3};"
        : "+f"(c[0]), "+f"(c[1]), "+f"(c[2]), "+f"(c[3])
        : "r"(a[0]), "r"(a[1]), "r"(a[2]), "r"(a[3]), "r"(b[0]), "r"(b[1]));
}
#define LDSM4(r0, r1, r2, r3, addr) \
    asm volatile("ldmatrix.sync.aligned.m8n8.x4.shared.b16 {%0,%1,%2,%3}, [%4];" \
                 : "=r"(r0), "=r"(r1), "=r"(r2), "=r"(r3) : "r"(addr))
#define CP16(dst, src, sz) \
    asm volatile("cp.async.cg.shared.global [%0], [%1], 16, %2;" :: "r"(dst), "l"(src), "r"(sz) : "memory")
#define CP_COMMIT() asm volatile("cp.async.commit_group;" ::: "memory")
#define CP_WAIT(n)  asm volatile("cp.async.wait_group %0;" :: "n"(n) : "memory")

#define STR 24            // halfs per smem row (48 B) -> conflict-free LDSM & cp.async
#define TILEH (128*STR)   // halfs per tile (6 KB)

template <int KIND>
__global__ __launch_bounds__(256, 2)
void gemm_kernel(const float* __restrict__ bias, float* __restrict__ outp)
{
    constexpr bool BUCKET = (KIND != KK && KIND != KV);
    constexpr int  KDIM = (KIND == KF2) ? Fn : (KIND == KPV ? Sn : Hn);
    constexpr int  NC   = KDIM / 16;

    const int tid  = threadIdx.x;
    const int wid  = tid >> 5;
    const int lane = tid & 31;
    const int z = blockIdx.z;
    int e, bb = 0, M;
    if (BUCKET) {
        e = z >> 2; bb = z & 3;
        M = g_cnt[z];
        if ((int)(blockIdx.x * 128) >= M) return;
    } else {
        e = z; M = Tn;
    }

    const int row0 = blockIdx.x * 128;
    const int col0 = blockIdx.y * 128;

    // ---- per-thread loader: row idx (0..127), granule s (0/1 -> 8 halfs) ----
    const int lrow = tid & 127;
    const int s    = tid >> 7;
    const int grow = row0 + lrow;
    const bool aval = BUCKET ? (grow < M) : true;
    const unsigned avsz = aval ? 16u : 0u;

    // A row base (k-major, row length = KDIM)
    const __half* aPtr = nullptr;
    if (aval) {
        if      (KIND == KK || KIND == KV)   aPtr = g_xh + (size_t)grow * Hn;
        else if (KIND == KQ || KIND == KF1)  aPtr = g_xh + (size_t)g_tok[z * CAPn + grow] * Hn;
        else if (KIND == KF2)                aPtr = g_h1h  + ((size_t)z * CAPn + grow) * Fn;
        else if (KIND == KSC)                aPtr = g_qh   + ((size_t)z * CAPn + grow) * Hn;
        else if (KIND == KPV)                aPtr = g_atth + ((size_t)z * CAPn + grow) * Sn;
        else                                 aPtr = g_ah   + ((size_t)z * CAPn + grow) * Hn;  // KO
        aPtr += s * 8;
    }
    // B row base ([n][k] row-major fp16)
    const __half* bPtr;
    if      (KIND == KK)  bPtr = g_kwT + ((size_t)e * Hn + col0 + lrow) * Hn;
    else if (KIND == KV)  bPtr = g_vwT + ((size_t)e * Hn + col0 + lrow) * Hn;
    else if (KIND == KQ)  bPtr = g_qwT + ((size_t)e * Hn + col0 + lrow) * Hn;
    else if (KIND == KO)  bPtr = g_owT + ((size_t)e * Hn + col0 + lrow) * Hn;
    else if (KIND == KF1) bPtr = g_f1T + ((size_t)e * Fn + col0 + lrow) * Hn;
    else if (KIND == KF2) bPtr = g_f2T + ((size_t)e * Hn + col0 + lrow) * Fn;
    else if (KIND == KSC) bPtr = g_Kh  + ((size_t)e * Tn + (size_t)bb * Sn + col0 + lrow) * Hn;
    else                  bPtr = g_Vth + ((size_t)e * Hn + col0 + lrow) * Tn + bb * Sn;  // KPV
    bPtr += s * 8;

    __shared__ __align__(16) __half smh[6 * TILEH];   // 3 stages x (A,B) = 36 KB
    const uint32_t sb = smem_u32(smh);
    const uint32_t aDst = sb + (lrow * STR + s * 8) * 2;
    const uint32_t bDst = sb + 3 * TILEH * 2 + (lrow * STR + s * 8) * 2;

    float acc[4][4][4];
#pragma unroll
    for (int i = 0; i < 4; i++)
#pragma unroll
        for (int j = 0; j < 4; j++)
#pragma unroll
            for (int k = 0; k < 4; k++) acc[i][j][k] = 0.f;

    const int wm  = (wid >> 2) * 64;
    const int wn  = (wid & 3) * 32;
    const int grp = lane >> 2;
    const int tg  = lane & 3;

    // ldmatrix lane addresses (within a stage tile)
    const int arow = wm + (lane & 7) + ((lane >> 3) & 1) * 8;
    const int agr  = lane >> 4;
    const uint32_t aLd0 = sb + (arow * STR + agr * 8) * 2;
    const int brow = wn + (lane & 7) + ((lane >= 16) ? 8 : 0);
    const int bgr  = (lane >> 3) & 1;
    const uint32_t bLd0 = sb + 3 * TILEH * 2 + (brow * STR + bgr * 8) * 2;

    auto issue = [&](int st, int c) {
        CP16(aDst + st * TILEH * 2, aPtr + c * 16, avsz);
        CP16(bDst + st * TILEH * 2, bPtr + c * 16, 16u);
        CP_COMMIT();
    };

    issue(0, 0);
    issue(1, 1);

    for (int c = 0; c < NC; c++) {
        if (c + 1 < NC) { CP_WAIT(1); } else { CP_WAIT(0); }
        __syncthreads();
        if (c + 2 < NC) issue((c + 2) % 3, c + 2);

        const uint32_t off = ((c % 3) * TILEH) * 2;
        unsigned int af[4][4], bf[4][2];
#pragma unroll
        for (int mt = 0; mt < 4; mt++)
            LDSM4(af[mt][0], af[mt][1], af[mt][2], af[mt][3], aLd0 + off + mt * 16 * STR * 2);
        {
            unsigned int r0, r1, r2, r3;
            LDSM4(r0, r1, r2, r3, bLd0 + off);
            bf[0][0] = r0; bf[0][1] = r1; bf[1][0] = r2; bf[1][1] = r3;
            LDSM4(r0, r1, r2, r3, bLd0 + off + 16 * STR * 2);
            bf[2][0] = r0; bf[2][1] = r1; bf[3][0] = r2; bf[3][1] = r3;
        }
#pragma unroll
        for (int mt = 0; mt < 4; mt++)
#pragma unroll
            for (int nt = 0; nt < 4; nt++)
                mma_f16_16x8x16(acc[mt][nt], af[mt], bf[nt]);
    }

    // ---------------- epilogue ----------------
#pragma unroll
    for (int mt = 0; mt < 4; mt++) {
#pragma unroll
        for (int half = 0; half < 2; half++) {
            const int r = row0 + wm + mt * 16 + grp + half * 8;
            if (BUCKET && r >= M) continue;

            if (KIND == KK) {
                __half* C = g_Kh + ((size_t)e * Tn + r) * Hn;
                const float* bp = bias + (size_t)e * Hn;
#pragma unroll
                for (int nt = 0; nt < 4; nt++) {
                    const int c = col0 + wn + nt * 8 + tg * 2;
                    float2 bv = *(const float2*)(bp + c);
                    *(unsigned int*)(C + c) = f22u(acc[mt][nt][half*2] + bv.x,
                                                   acc[mt][nt][half*2+1] + bv.y);
                }
            } else if (KIND == KV) {
                // transposed store: Vth[e][c][r]
                const float* bp = bias + (size_t)e * Hn;
                __half* Vb = g_Vth + (size_t)e * Hn * Tn + r;
#pragma unroll
                for (int nt = 0; nt < 4; nt++) {
                    const int c = col0 + wn + nt * 8 + tg * 2;
                    float2 bv = *(const float2*)(bp + c);
                    Vb[(size_t)c * Tn]       = __float2half_rn(acc[mt][nt][half*2]   + bv.x);
                    Vb[(size_t)(c + 1) * Tn] = __float2half_rn(acc[mt][nt][half*2+1] + bv.y);
                }
            } else if (KIND == KQ) {
                __half* C = g_qh + ((size_t)z * CAPn + r) * Hn;
                const float* bp = bias + (size_t)e * Hn;
#pragma unroll
                for (int nt = 0; nt < 4; nt++) {
                    const int c = col0 + wn + nt * 8 + tg * 2;
                    float2 bv = *(const float2*)(bp + c);
                    *(unsigned int*)(C + c) = f22u(acc[mt][nt][half*2] + bv.x,
                                                   acc[mt][nt][half*2+1] + bv.y);
                }
            } else if (KIND == KF1) {
                __half* C = g_h1h + ((size_t)z * CAPn + r) * Fn;
                const float* bp = bias + (size_t)e * Fn;
#pragma unroll
                for (int nt = 0; nt < 4; nt++) {
                    const int c = col0 + wn + nt * 8 + tg * 2;
                    float2 bv = *(const float2*)(bp + c);
                    float t0 = acc[mt][nt][half*2]   + bv.x;
                    float t1 = acc[mt][nt][half*2+1] + bv.y;
                    t0 = 0.5f * t0 * (1.0f + erff(t0 * 0.70710678118654752f));
                    t1 = 0.5f * t1 * (1.0f + erff(t1 * 0.70710678118654752f));
                    *(unsigned int*)(C + c) = f22u(t0, t1);
                }
            } else if (KIND == KF2) {
                float* C = g_h2 + ((size_t)z * CAPn + r) * Hn;
                const float* bp = bias + (size_t)e * Hn;
#pragma unroll
                for (int nt = 0; nt < 4; nt++) {
                    const int c = col0 + wn + nt * 8 + tg * 2;
                    float2 bv = *(const float2*)(bp + c);
                    float2 v = make_float2(acc[mt][nt][half*2]   + bv.x,
                                           acc[mt][nt][half*2+1] + bv.y);
                    *(float2*)(C + c) = v;
                }
            } else if (KIND == KSC) {
                const float scl = 0.044194173824159216f;  // 1/sqrt(512)
                float* C = g_sc + ((size_t)z * CAPn + r) * Sn;
#pragma unroll
                for (int nt = 0; nt < 4; nt++) {
                    const int c = col0 + wn + nt * 8 + tg * 2;
                    float2 v = make_float2(acc[mt][nt][half*2]   * scl,
                                           acc[mt][nt][half*2+1] * scl);
                    *(float2*)(C + c) = v;
                }
            } else if (KIND == KPV) {
                __half* C = g_ah + ((size_t)z * CAPn + r) * Hn;
#pragma unroll
                for (int nt = 0; nt < 4; nt++) {
                    const int c = col0 + wn + nt * 8 + tg * 2;
                    *(unsigned int*)(C + c) = f22u(acc[mt][nt][half*2], acc[mt][nt][half*2+1]);
                }
            } else {  // KO
                const int tok = g_tok[z * CAPn + r];
                const float wt = g_wt[z * CAPn + r];
                const float* bp = bias + (size_t)e * Hn;
                const float* h2 = g_h2 + ((size_t)z * CAPn + r) * Hn;
                float* od = outp + (size_t)tok * Hn;
#pragma unroll
                for (int nt = 0; nt < 4; nt++) {
                    const int c = col0 + wn + nt * 8 + tg * 2;
                    float v0 = acc[mt][nt][half*2]   + bp[c]   + h2[c];
                    float v1 = acc[mt][nt][half*2+1] + bp[c+1] + h2[c+1];
                    atomicAdd(od + c,     wt * v0);
                    atomicAdd(od + c + 1, wt * v1);
                }
            }
        }
    }
}

// ---------------- launch ----------------
extern "C" void kernel_launch(void* const* d_in, const int* in_sizes, int n_in,
                              void* d_out, int out_size)
{
    const float* x    = (const float*)d_in[0];
    const float* Wg   = (const float*)d_in[1];
    const float* bg   = (const float*)d_in[2];
    const float* fc1w = (const float*)d_in[3];
    const float* fc1b = (const float*)d_in[4];
    const float* fc2w = (const float*)d_in[5];
    const float* fc2b = (const float*)d_in[6];
    const float* qw   = (const float*)d_in[7];
    const float* qb   = (const float*)d_in[8];
    const float* kw   = (const float*)d_in[9];
    const float* kb   = (const float*)d_in[10];
    const float* vw   = (const float*)d_in[11];
    const float* vb   = (const float*)d_in[12];
    const float* ow   = (const float*)d_in[13];
    const float* ob   = (const float*)d_in[14];
    float* out = (float*)d_out;

    __half* dxh;  cudaGetSymbolAddress((void**)&dxh,  g_xh);
    __half* dqwT; cudaGetSymbolAddress((void**)&dqwT, g_qwT);
    __half* dkwT; cudaGetSymbolAddress((void**)&dkwT, g_kwT);
    __half* dvwT; cudaGetSymbolAddress((void**)&dvwT, g_vwT);
    __half* dowT; cudaGetSymbolAddress((void**)&dowT, g_owT);
    __half* df1T; cudaGetSymbolAddress((void**)&df1T, g_f1T);
    __half* df2T; cudaGetSymbolAddress((void**)&df2T, g_f2T);

    reset_kernel<<<1, 64>>>();
    zero_kernel<<<(out_size + 255) / 256, 256>>>(out, out_size);

    halve_kernel<<<(Tn * Hn / 4 + 255) / 256, 256>>>(x, dxh, Tn * Hn);
    dim3 tb(32, 8);
    transpose_h_kernel<<<dim3(Hn / 32, Hn / 32, En), tb>>>(qw, dqwT, Hn, Hn);
    transpose_h_kernel<<<dim3(Hn / 32, Hn / 32, En), tb>>>(kw, dkwT, Hn, Hn);
    transpose_h_kernel<<<dim3(Hn / 32, Hn / 32, En), tb>>>(vw, dvwT, Hn, Hn);
    transpose_h_kernel<<<dim3(Hn / 32, Hn / 32, En), tb>>>(ow, dowT, Hn, Hn);
    transpose_h_kernel<<<dim3(Fn / 32, Hn / 32, En), tb>>>(fc1w, df1T, Hn, Fn);
    transpose_h_kernel<<<dim3(Hn / 32, Fn / 32, En), tb>>>(fc2w, df2T, Fn, Hn);

    router_kernel<<<Tn / 8, 256>>>(x, Wg, bg);

    dim3 gkv(Tn / 128, Hn / 128, En);
    gemm_kernel<KK><<<gkv, 256>>>(kb, nullptr);
    gemm_kernel<KV><<<gkv, 256>>>(vb, nullptr);

    gemm_kernel<KQ ><<<dim3(CAPn / 128, Hn / 128, NBUCK), 256>>>(qb, nullptr);
    gemm_kernel<KF1><<<dim3(CAPn / 128, Fn / 128, NBUCK), 256>>>(fc1b, nullptr);
    gemm_kernel<KF2><<<dim3(CAPn / 128, Hn / 128, NBUCK), 256>>>(fc2b, nullptr);
    gemm_kernel<KSC><<<dim3(CAPn / 128, Sn / 128, NBUCK), 256>>>(nullptr, nullptr);

    softmax_kernel<<<NBUCK * CAPn, 256>>>();

    gemm_kernel<KPV><<<dim3(CAPn / 128, Hn / 128, NBUCK), 256>>>(nullptr, nullptr);
    gemm_kernel<KO ><<<dim3(CAPn / 128, Hn / 128, NBUCK), 256>>>(ob, out);

    finalize_kernel<<<1, 32>>>(out, out_size);
}

// round 8
// speedup vs baseline: 2.3156x; 1.1345x over previous
#include <cuda_runtime.h>
#include <cuda_fp16.h>
#include <math.h>
#include <stdint.h>

// Problem constants
#define Bn 4
#define Sn 1024
#define Tn 4096          // Bn*Sn tokens
#define Hn 512
#define En 8
#define Fn 2048
#define NBUCK 32         // En*Bn  (expert, batch) buckets
#define CAPn 1024        // max tokens per bucket = Sn

// ---------------- scratch (__device__ globals; no allocation) ----------------
__device__ __half g_xh  [(size_t)Tn*Hn];
__device__ __half g_Kh  [(size_t)En*Tn*Hn];
__device__ __half g_Vth [(size_t)En*Hn*Tn];          // V TRANSPOSED [e][h][t]
__device__ __half g_qh  [(size_t)NBUCK*CAPn*Hn];
__device__ __half g_h1h [(size_t)NBUCK*CAPn*Fn];
__device__ __half g_atth[(size_t)NBUCK*CAPn*Sn];
__device__ __half g_ah  [(size_t)NBUCK*CAPn*Hn];
__device__ __half g_qwT[(size_t)En*Hn*Hn];
__device__ __half g_kwT[(size_t)En*Hn*Hn];
__device__ __half g_vwT[(size_t)En*Hn*Hn];
__device__ __half g_owT[(size_t)En*Hn*Hn];
__device__ __half g_f1T[(size_t)En*Fn*Hn];
__device__ __half g_f2T[(size_t)En*Hn*Fn];
__device__ float g_sc[(size_t)NBUCK*CAPn*Sn];
__device__ float g_h2[(size_t)NBUCK*CAPn*Hn];
__device__ int   g_cnt[NBUCK];
__device__ int   g_tok[NBUCK*CAPn];
__device__ float g_wt [NBUCK*CAPn];
__device__ float g_imp[En];

__device__ __forceinline__ unsigned int f22u(float a, float b) {
    __half2 h = __floats2half2_rn(a, b);
    return *(unsigned int*)&h;
}
__device__ __forceinline__ uint32_t smem_u32(const void* p) {
    uint32_t a;
    asm("{ .reg .u64 t; cvta.to.shared.u64 t, %1; cvt.u32.u64 %0, t; }" : "=r"(a) : "l"(p));
    return a;
}

// ---------------- small kernels ----------------
__global__ void reset_kernel() {
    int i = threadIdx.x;
    if (i < NBUCK) g_cnt[i] = 0;
    if (i < En)    g_imp[i] = 0.f;
}

__global__ void zero_kernel(float* __restrict__ out, int n) {
    int i = blockIdx.x * blockDim.x + threadIdx.x;
    if (i < n) out[i] = 0.f;
}

__global__ void halve_kernel(const float* __restrict__ src, __half* __restrict__ dst, int n) {
    int i = (blockIdx.x * blockDim.x + threadIdx.x) * 4;
    if (i < n) {
        float4 v = *(const float4*)(src + i);
        uint2 o = make_uint2(f22u(v.x, v.y), f22u(v.z, v.w));
        *(uint2*)(dst + i) = o;
    }
}

// fp32 [E][R][C] -> fp16 [E][C][R]
__global__ void transpose_h_kernel(const float* __restrict__ in, __half* __restrict__ out,
                                   int R, int C)
{
    __shared__ float t[32][33];
    int e = blockIdx.z;
    const float* src = in + (size_t)e * R * C;
    __half* dst = out + (size_t)e * R * C;
    int c0 = blockIdx.x * 32, r0 = blockIdx.y * 32;
    int x = threadIdx.x, y = threadIdx.y;   // (32, 8)
#pragma unroll
    for (int i = 0; i < 32; i += 8)
        t[y + i][x] = src[(size_t)(r0 + y + i) * C + c0 + x];
    __syncthreads();
#pragma unroll
    for (int i = 0; i < 32; i += 8)
        dst[(size_t)(c0 + y + i) * R + r0 + x] = __float2half_rn(t[x][y + i]);
}

// Router: one warp per token. Exact fp32.
__global__ void router_kernel(const float* __restrict__ x,
                              const float* __restrict__ Wg,
                              const float* __restrict__ bg)
{
    int warp = (blockIdx.x * blockDim.x + threadIdx.x) >> 5;
    int lane = threadIdx.x & 31;
    if (warp >= Tn) return;
    const int t = warp;

    float acc[En];
#pragma unroll
    for (int e = 0; e < En; e++) acc[e] = 0.f;

    for (int h = lane; h < Hn; h += 32) {
        float xv = x[(size_t)t * Hn + h];
        float4 w0 = *(const float4*)(Wg + (size_t)h * En);
        float4 w1 = *(const float4*)(Wg + (size_t)h * En + 4);
        acc[0] += xv * w0.x; acc[1] += xv * w0.y; acc[2] += xv * w0.z; acc[3] += xv * w0.w;
        acc[4] += xv * w1.x; acc[5] += xv * w1.y; acc[6] += xv * w1.z; acc[7] += xv * w1.w;
    }
#pragma unroll
    for (int off = 16; off > 0; off >>= 1) {
#pragma unroll
        for (int e = 0; e < En; e++)
            acc[e] += __shfl_xor_sync(0xffffffffu, acc[e], off);
    }
    if (lane != 0) return;

    float p[En];
    float m = -1e30f;
#pragma unroll
    for (int e = 0; e < En; e++) { p[e] = acc[e] + bg[e]; m = fmaxf(m, p[e]); }
    float s = 0.f;
#pragma unroll
    for (int e = 0; e < En; e++) { p[e] = expf(p[e] - m); s += p[e]; }
    float inv = 1.0f / s;
#pragma unroll
    for (int e = 0; e < En; e++) { p[e] *= inv; atomicAdd(&g_imp[e], p[e]); }

    int i1 = 0;
#pragma unroll
    for (int e = 1; e < En; e++) if (p[e] > p[i1]) i1 = e;
    int i2 = (i1 == 0) ? 1 : 0;
#pragma unroll
    for (int e = 0; e < En; e++) if (e != i1 && p[e] > p[i2]) i2 = e;

    float denom = p[i1] + p[i2];
    int b = t >> 10;
    int bk1 = i1 * Bn + b;
    int pos1 = atomicAdd(&g_cnt[bk1], 1);
    g_tok[bk1 * CAPn + pos1] = t;
    g_wt [bk1 * CAPn + pos1] = p[i1] / denom;
    int bk2 = i2 * Bn + b;
    int pos2 = atomicAdd(&g_cnt[bk2], 1);
    g_tok[bk2 * CAPn + pos2] = t;
    g_wt [bk2 * CAPn + pos2] = p[i2] / denom;
}

// Row softmax: read fp32 scores, write fp16 probs.
__global__ void softmax_kernel()
{
    int bkt = blockIdx.x >> 10;
    int r   = blockIdx.x & (CAPn - 1);
    if (r >= g_cnt[bkt]) return;
    const float* row = g_sc + ((size_t)bkt * CAPn + r) * Sn;
    __half* orow = g_atth + ((size_t)bkt * CAPn + r) * Sn;
    int tid = threadIdx.x;

    float4 v = *(const float4*)(row + tid * 4);
    float m = fmaxf(fmaxf(v.x, v.y), fmaxf(v.z, v.w));

    __shared__ float sm[8];
    __shared__ float bcast;
#pragma unroll
    for (int off = 16; off > 0; off >>= 1)
        m = fmaxf(m, __shfl_xor_sync(0xffffffffu, m, off));
    if ((tid & 31) == 0) sm[tid >> 5] = m;
    __syncthreads();
    if (tid == 0) {
        float mm = sm[0];
#pragma unroll
        for (int k = 1; k < 8; k++) mm = fmaxf(mm, sm[k]);
        bcast = mm;
    }
    __syncthreads();
    float bm = bcast;

    v.x = expf(v.x - bm); v.y = expf(v.y - bm);
    v.z = expf(v.z - bm); v.w = expf(v.w - bm);
    float ssum = v.x + v.y + v.z + v.w;
#pragma unroll
    for (int off = 16; off > 0; off >>= 1)
        ssum += __shfl_xor_sync(0xffffffffu, ssum, off);
    if ((tid & 31) == 0) sm[tid >> 5] = ssum;
    __syncthreads();
    if (tid == 0) {
        float tt = 0.f;
#pragma unroll
        for (int k = 0; k < 8; k++) tt += sm[k];
        bcast = 1.0f / tt;
    }
    __syncthreads();
    float invs = bcast;
    uint2 o = make_uint2(f22u(v.x * invs, v.y * invs), f22u(v.z * invs, v.w * invs));
    *(uint2*)(orow + tid * 4) = o;
}

__global__ void finalize_kernel(float* __restrict__ out, int out_size)
{
    if (threadIdx.x == 0 && out_size > Tn * Hn) {
        float loss = 0.f;
        for (int e = 0; e < En; e++) {
            int a = 0;
            for (int b = 0; b < Bn; b++) a += g_cnt[e * Bn + b];
            loss += ((float)a / (float)Tn) * (g_imp[e] / (float)Tn);
        }
        out[Tn * Hn] = (float)En * loss;
    }
}

// ---------------- fp16 mma GEMM: 128x128 tile, 8 warps 64x32, cp.async + ldmatrix ----------------
enum { KK = 0, KV = 1, KQ = 2, KF1 = 3, KF2 = 4, KSC = 5, KPV = 6, KO = 7 };

__device__ __forceinline__ void mma_f16_16x8x16(float* c, const unsigned int* a, const unsigned int* b) {
    asm volatile(
        "mma.sync.aligned.m16n8k16.row.col.f32.f16.f16.f32 "
        "{%0,%1,%2,%3}, {%4,%5,%6,%7}, {%8,%9}, {%0,%1,%2,%3};"
        : "+f"(c[0]), "+f"(c[1]), "+f"(c[2]), "+f"(c[3])
        : "r"(a[0]), "r"(a[1]), "r"(a[2]), "r"(a[3]), "r"(b[0]), "r"(b[1]));
}
#define LDSM4(r0, r1, r2, r3, addr) \
    asm volatile("ldmatrix.sync.aligned.m8n8.x4.shared.b16 {%0,%1,%2,%3}, [%4];" \
                 : "=r"(r0), "=r"(r1), "=r"(r2), "=r"(r3) : "r"(addr))
#define CP16(dst, src, sz) \
    asm volatile("cp.async.cg.shared.global [%0], [%1], 16, %2;" :: "r"(dst), "l"(src), "r"(sz) : "memory")
#define CP_COMMIT() asm volatile("cp.async.commit_group;" ::: "memory")
#define CP_WAIT(n)  asm volatile("cp.async.wait_group %0;" :: "n"(n) : "memory")

#define STR 24            // halfs per smem row (48 B) -> conflict-free LDSM & cp.async
#define TILEH (128*STR)   // halfs per tile (6 KB)

template <int KIND>
__global__ __launch_bounds__(256, 2)
void gemm_kernel(const float* __restrict__ bias, float* __restrict__ outp)
{
    constexpr bool BUCKET = (KIND != KK && KIND != KV);
    constexpr int  KDIM = (KIND == KF2) ? Fn : (KIND == KPV ? Sn : Hn);
    constexpr int  NC   = KDIM / 16;

    const int tid  = threadIdx.x;
    const int wid  = tid >> 5;
    const int lane = tid & 31;
    const int z = blockIdx.z;
    int e, bb = 0, M;
    if (BUCKET) {
        e = z >> 2; bb = z & 3;
        M = g_cnt[z];
        if ((int)(blockIdx.x * 128) >= M) return;
    } else {
        e = z; M = Tn;
    }

    const int row0 = blockIdx.x * 128;
    const int col0 = blockIdx.y * 128;

    const int lrow = tid & 127;
    const int s    = tid >> 7;
    const int grow = row0 + lrow;
    const bool aval = BUCKET ? (grow < M) : true;
    const unsigned avsz = aval ? 16u : 0u;

    const __half* aPtr = nullptr;
    if (aval) {
        if      (KIND == KK || KIND == KV)   aPtr = g_xh + (size_t)grow * Hn;
        else if (KIND == KQ || KIND == KF1)  aPtr = g_xh + (size_t)g_tok[z * CAPn + grow] * Hn;
        else if (KIND == KF2)                aPtr = g_h1h  + ((size_t)z * CAPn + grow) * Fn;
        else if (KIND == KSC)                aPtr = g_qh   + ((size_t)z * CAPn + grow) * Hn;
        else if (KIND == KPV)                aPtr = g_atth + ((size_t)z * CAPn + grow) * Sn;
        else                                 aPtr = g_ah   + ((size_t)z * CAPn + grow) * Hn;  // KO
        aPtr += s * 8;
    }
    const __half* bPtr;
    if      (KIND == KK)  bPtr = g_kwT + ((size_t)e * Hn + col0 + lrow) * Hn;
    else if (KIND == KV)  bPtr = g_vwT + ((size_t)e * Hn + col0 + lrow) * Hn;
    else if (KIND == KQ)  bPtr = g_qwT + ((size_t)e * Hn + col0 + lrow) * Hn;
    else if (KIND == KO)  bPtr = g_owT + ((size_t)e * Hn + col0 + lrow) * Hn;
    else if (KIND == KF1) bPtr = g_f1T + ((size_t)e * Fn + col0 + lrow) * Hn;
    else if (KIND == KF2) bPtr = g_f2T + ((size_t)e * Hn + col0 + lrow) * Fn;
    else if (KIND == KSC) bPtr = g_Kh  + ((size_t)e * Tn + (size_t)bb * Sn + col0 + lrow) * Hn;
    else                  bPtr = g_Vth + ((size_t)e * Hn + col0 + lrow) * Tn + bb * Sn;  // KPV
    bPtr += s * 8;

    __shared__ __align__(16) __half smh[6 * TILEH];   // 3 stages x (A,B) = 36 KB
    const uint32_t sb = smem_u32(smh);
    const uint32_t aDst = sb + (lrow * STR + s * 8) * 2;
    const uint32_t bDst = sb + 3 * TILEH * 2 + (lrow * STR + s * 8) * 2;

    float acc[4][4][4];
#pragma unroll
    for (int i = 0; i < 4; i++)
#pragma unroll
        for (int j = 0; j < 4; j++)
#pragma unroll
            for (int k = 0; k < 4; k++) acc[i][j][k] = 0.f;

    const int wm  = (wid >> 2) * 64;
    const int wn  = (wid & 3) * 32;
    const int grp = lane >> 2;
    const int tg  = lane & 3;

    const int arow = wm + (lane & 7) + ((lane >> 3) & 1) * 8;
    const int agr  = lane >> 4;
    const uint32_t aLd0 = sb + (arow * STR + agr * 8) * 2;
    const int brow = wn + (lane & 7) + ((lane >= 16) ? 8 : 0);
    const int bgr  = (lane >> 3) & 1;
    const uint32_t bLd0 = sb + 3 * TILEH * 2 + (brow * STR + bgr * 8) * 2;

    auto issue = [&](int st, int c) {
        CP16(aDst + st * TILEH * 2, aPtr + c * 16, avsz);
        CP16(bDst + st * TILEH * 2, bPtr + c * 16, 16u);
        CP_COMMIT();
    };

    issue(0, 0);
    issue(1, 1);

    for (int c = 0; c < NC; c++) {
        if (c + 1 < NC) { CP_WAIT(1); } else { CP_WAIT(0); }
        __syncthreads();
        if (c + 2 < NC) issue((c + 2) % 3, c + 2);

        const uint32_t off = ((c % 3) * TILEH) * 2;
        unsigned int af[4][4], bf[4][2];
#pragma unroll
        for (int mt = 0; mt < 4; mt++)
            LDSM4(af[mt][0], af[mt][1], af[mt][2], af[mt][3], aLd0 + off + mt * 16 * STR * 2);
        {
            unsigned int r0, r1, r2, r3;
            LDSM4(r0, r1, r2, r3, bLd0 + off);
            bf[0][0] = r0; bf[0][1] = r1; bf[1][0] = r2; bf[1][1] = r3;
            LDSM4(r0, r1, r2, r3, bLd0 + off + 16 * STR * 2);
            bf[2][0] = r0; bf[2][1] = r1; bf[3][0] = r2; bf[3][1] = r3;
        }
#pragma unroll
        for (int mt = 0; mt < 4; mt++)
#pragma unroll
            for (int nt = 0; nt < 4; nt++)
                mma_f16_16x8x16(acc[mt][nt], af[mt], bf[nt]);
    }

    // ---------------- epilogue ----------------
#pragma unroll
    for (int mt = 0; mt < 4; mt++) {
#pragma unroll
        for (int half = 0; half < 2; half++) {
            const int r = row0 + wm + mt * 16 + grp + half * 8;
            if (BUCKET && r >= M) continue;

            if (KIND == KK) {
                __half* C = g_Kh + ((size_t)e * Tn + r) * Hn;
                const float* bp = bias + (size_t)e * Hn;
#pragma unroll
                for (int nt = 0; nt < 4; nt++) {
                    const int c = col0 + wn + nt * 8 + tg * 2;
                    float2 bv = *(const float2*)(bp + c);
                    *(unsigned int*)(C + c) = f22u(acc[mt][nt][half*2] + bv.x,
                                                   acc[mt][nt][half*2+1] + bv.y);
                }
            } else if (KIND == KV) {
                const float* bp = bias + (size_t)e * Hn;
                __half* Vb = g_Vth + (size_t)e * Hn * Tn + r;
#pragma unroll
                for (int nt = 0; nt < 4; nt++) {
                    const int c = col0 + wn + nt * 8 + tg * 2;
                    float2 bv = *(const float2*)(bp + c);
                    Vb[(size_t)c * Tn]       = __float2half_rn(acc[mt][nt][half*2]   + bv.x);
                    Vb[(size_t)(c + 1) * Tn] = __float2half_rn(acc[mt][nt][half*2+1] + bv.y);
                }
            } else if (KIND == KQ) {
                __half* C = g_qh + ((size_t)z * CAPn + r) * Hn;
                const float* bp = bias + (size_t)e * Hn;
#pragma unroll
                for (int nt = 0; nt < 4; nt++) {
                    const int c = col0 + wn + nt * 8 + tg * 2;
                    float2 bv = *(const float2*)(bp + c);
                    *(unsigned int*)(C + c) = f22u(acc[mt][nt][half*2] + bv.x,
                                                   acc[mt][nt][half*2+1] + bv.y);
                }
            } else if (KIND == KF1) {
                __half* C = g_h1h + ((size_t)z * CAPn + r) * Fn;
                const float* bp = bias + (size_t)e * Fn;
#pragma unroll
                for (int nt = 0; nt < 4; nt++) {
                    const int c = col0 + wn + nt * 8 + tg * 2;
                    float2 bv = *(const float2*)(bp + c);
                    float t0 = acc[mt][nt][half*2]   + bv.x;
                    float t1 = acc[mt][nt][half*2+1] + bv.y;
                    t0 = 0.5f * t0 * (1.0f + erff(t0 * 0.70710678118654752f));
                    t1 = 0.5f * t1 * (1.0f + erff(t1 * 0.70710678118654752f));
                    *(unsigned int*)(C + c) = f22u(t0, t1);
                }
            } else if (KIND == KF2) {
                float* C = g_h2 + ((size_t)z * CAPn + r) * Hn;
                const float* bp = bias + (size_t)e * Hn;
#pragma unroll
                for (int nt = 0; nt < 4; nt++) {
                    const int c = col0 + wn + nt * 8 + tg * 2;
                    float2 bv = *(const float2*)(bp + c);
                    float2 v = make_float2(acc[mt][nt][half*2]   + bv.x,
                                           acc[mt][nt][half*2+1] + bv.y);
                    *(float2*)(C + c) = v;
                }
            } else if (KIND == KSC) {
                const float scl = 0.044194173824159216f;  // 1/sqrt(512)
                float* C = g_sc + ((size_t)z * CAPn + r) * Sn;
#pragma unroll
                for (int nt = 0; nt < 4; nt++) {
                    const int c = col0 + wn + nt * 8 + tg * 2;
                    float2 v = make_float2(acc[mt][nt][half*2]   * scl,
                                           acc[mt][nt][half*2+1] * scl);
                    *(float2*)(C + c) = v;
                }
            } else if (KIND == KPV) {
                __half* C = g_ah + ((size_t)z * CAPn + r) * Hn;
#pragma unroll
                for (int nt = 0; nt < 4; nt++) {
                    const int c = col0 + wn + nt * 8 + tg * 2;
                    *(unsigned int*)(C + c) = f22u(acc[mt][nt][half*2], acc[mt][nt][half*2+1]);
                }
            } else {  // KO
                const int tok = g_tok[z * CAPn + r];
                const float wt = g_wt[z * CAPn + r];
                const float* bp = bias + (size_t)e * Hn;
                const float* h2 = g_h2 + ((size_t)z * CAPn + r) * Hn;
                float* od = outp + (size_t)tok * Hn;
#pragma unroll
                for (int nt = 0; nt < 4; nt++) {
                    const int c = col0 + wn + nt * 8 + tg * 2;
                    float v0 = acc[mt][nt][half*2]   + bp[c]   + h2[c];
                    float v1 = acc[mt][nt][half*2+1] + bp[c+1] + h2[c+1];
                    atomicAdd(od + c,     wt * v0);
                    atomicAdd(od + c + 1, wt * v1);
                }
            }
        }
    }
}

// ---------------- launch: forked-stream graph ----------------
extern "C" void kernel_launch(void* const* d_in, const int* in_sizes, int n_in,
                              void* d_out, int out_size)
{
    const float* x    = (const float*)d_in[0];
    const float* Wg   = (const float*)d_in[1];
    const float* bg   = (const float*)d_in[2];
    const float* fc1w = (const float*)d_in[3];
    const float* fc1b = (const float*)d_in[4];
    const float* fc2w = (const float*)d_in[5];
    const float* fc2b = (const float*)d_in[6];
    const float* qw   = (const float*)d_in[7];
    const float* qb   = (const float*)d_in[8];
    const float* kw   = (const float*)d_in[9];
    const float* kb   = (const float*)d_in[10];
    const float* vw   = (const float*)d_in[11];
    const float* vb   = (const float*)d_in[12];
    const float* ow   = (const float*)d_in[13];
    const float* ob   = (const float*)d_in[14];
    float* out = (float*)d_out;

    __half* dxh;  cudaGetSymbolAddress((void**)&dxh,  g_xh);
    __half* dqwT; cudaGetSymbolAddress((void**)&dqwT, g_qwT);
    __half* dkwT; cudaGetSymbolAddress((void**)&dkwT, g_kwT);
    __half* dvwT; cudaGetSymbolAddress((void**)&dvwT, g_vwT);
    __half* dowT; cudaGetSymbolAddress((void**)&dowT, g_owT);
    __half* df1T; cudaGetSymbolAddress((void**)&df1T, g_f1T);
    __half* df2T; cudaGetSymbolAddress((void**)&df2T, g_f2T);

    // lazily created once (first call is the uncaptured correctness run)
    static cudaStream_t s1 = nullptr, s2 = nullptr, s3 = nullptr;
    static cudaEvent_t evStart, evBase, evT1, evKK, evKV, evF2;
    if (s1 == nullptr) {
        cudaStreamCreateWithFlags(&s1, cudaStreamNonBlocking);
        cudaStreamCreateWithFlags(&s2, cudaStreamNonBlocking);
        cudaStreamCreateWithFlags(&s3, cudaStreamNonBlocking);
        cudaEventCreateWithFlags(&evStart, cudaEventDisableTiming);
        cudaEventCreateWithFlags(&evBase,  cudaEventDisableTiming);
        cudaEventCreateWithFlags(&evT1,    cudaEventDisableTiming);
        cudaEventCreateWithFlags(&evKK,    cudaEventDisableTiming);
        cudaEventCreateWithFlags(&evKV,    cudaEventDisableTiming);
        cudaEventCreateWithFlags(&evF2,    cudaEventDisableTiming);
    }

    dim3 tb(32, 8);

    // ---- fork point ----
    cudaEventRecord(evStart, 0);
    cudaStreamWaitEvent(s1, evStart, 0);
    cudaStreamWaitEvent(s2, evStart, 0);
    cudaStreamWaitEvent(s3, evStart, 0);

    // s1: qw,kw transpose -> KK
    transpose_h_kernel<<<dim3(Hn / 32, Hn / 32, En), tb, 0, s1>>>(qw, dqwT, Hn, Hn);
    transpose_h_kernel<<<dim3(Hn / 32, Hn / 32, En), tb, 0, s1>>>(kw, dkwT, Hn, Hn);
    cudaEventRecord(evT1, s1);   // qw^T ready (for KQ on L)
    // s2: vw,ow transpose -> KV
    transpose_h_kernel<<<dim3(Hn / 32, Hn / 32, En), tb, 0, s2>>>(vw, dvwT, Hn, Hn);
    transpose_h_kernel<<<dim3(Hn / 32, Hn / 32, En), tb, 0, s2>>>(ow, dowT, Hn, Hn);
    // s3: f1,f2 transpose -> KF1 -> KF2
    transpose_h_kernel<<<dim3(Fn / 32, Hn / 32, En), tb, 0, s3>>>(fc1w, df1T, Hn, Fn);
    transpose_h_kernel<<<dim3(Hn / 32, Fn / 32, En), tb, 0, s3>>>(fc2w, df2T, Fn, Hn);

    // L: base prep + critical path
    reset_kernel<<<1, 64>>>();
    zero_kernel<<<(out_size + 255) / 256, 256>>>(out, out_size);
    halve_kernel<<<(Tn * Hn / 4 + 255) / 256, 256>>>(x, dxh, Tn * Hn);
    router_kernel<<<Tn / 8, 256>>>(x, Wg, bg);
    cudaEventRecord(evBase, 0);  // xh + buckets ready

    // side-stream GEMMs
    cudaStreamWaitEvent(s1, evBase, 0);
    gemm_kernel<KK><<<dim3(Tn / 128, Hn / 128, En), 256, 0, s1>>>(kb, nullptr);
    cudaEventRecord(evKK, s1);

    cudaStreamWaitEvent(s2, evBase, 0);
    gemm_kernel<KV><<<dim3(Tn / 128, Hn / 128, En), 256, 0, s2>>>(vb, nullptr);
    cudaEventRecord(evKV, s2);

    cudaStreamWaitEvent(s3, evBase, 0);
    gemm_kernel<KF1><<<dim3(CAPn / 128, Fn / 128, NBUCK), 256, 0, s3>>>(fc1b, nullptr);
    gemm_kernel<KF2><<<dim3(CAPn / 128, Hn / 128, NBUCK), 256, 0, s3>>>(fc2b, nullptr);
    cudaEventRecord(evF2, s3);

    // L critical path
    cudaStreamWaitEvent(0, evT1, 0);
    gemm_kernel<KQ><<<dim3(CAPn / 128, Hn / 128, NBUCK), 256>>>(qb, nullptr);
    cudaStreamWaitEvent(0, evKK, 0);
    gemm_kernel<KSC><<<dim3(CAPn / 128, Sn / 128, NBUCK), 256>>>(nullptr, nullptr);
    softmax_kernel<<<NBUCK * CAPn, 256>>>();
    cudaStreamWaitEvent(0, evKV, 0);
    gemm_kernel<KPV><<<dim3(CAPn / 128, Hn / 128, NBUCK), 256>>>(nullptr, nullptr);
    cudaStreamWaitEvent(0, evF2, 0);
    gemm_kernel<KO><<<dim3(CAPn / 128, Hn / 128, NBUCK), 256>>>(ob, out);

    finalize_kernel<<<1, 32>>>(out, out_size);
}